// round 1
// baseline (speedup 1.0000x reference)
#include <cuda_runtime.h>
#include <cuda_bf16.h>
#include <math.h>

#define T_TOK 8192
#define DIM   1024
#define HID   4096
#define NE    8

// Scratch (device globals — no allocations allowed)
__device__ float g_H[(size_t)T_TOK * HID];   // per-expert hidden activations (reused across experts)
__device__ int   g_entry[NE * T_TOK];        // packed token*2+k per expert slot
__device__ float g_topw[2 * T_TOK];          // top-2 softmax weights per token
__device__ int   g_cnt[NE];                  // tokens per expert
__device__ float g_usage[NE];                // sum of softmax probs per expert

// ---------------- init: zero out + counters ----------------
__global__ void init_kernel(float* out, int out_elems4) {
    int i = blockIdx.x * blockDim.x + threadIdx.x;
    if (i < out_elems4) ((float4*)out)[i] = make_float4(0.f, 0.f, 0.f, 0.f);
    if (i < NE) { g_cnt[i] = 0; g_usage[i] = 0.f; }
}

// ---------------- router: scores, top-2, dispatch, usage ----------------
__global__ void router_kernel(const float* __restrict__ x, const float* __restrict__ gw) {
    int warp = (blockIdx.x * blockDim.x + threadIdx.x) >> 5;
    int lane = threadIdx.x & 31;
    if (warp >= T_TOK) return;
    const float* xr = x + (size_t)warp * DIM;
    float acc[NE];
#pragma unroll
    for (int e = 0; e < NE; e++) acc[e] = 0.f;
    for (int d = lane; d < DIM; d += 32) {
        float xv = xr[d];
#pragma unroll
        for (int e = 0; e < NE; e++) acc[e] = fmaf(xv, gw[d * NE + e], acc[e]);
    }
#pragma unroll
    for (int off = 16; off; off >>= 1) {
#pragma unroll
        for (int e = 0; e < NE; e++) acc[e] += __shfl_xor_sync(0xffffffffu, acc[e], off);
    }
    if (lane == 0) {
        float m = acc[0];
#pragma unroll
        for (int e = 1; e < NE; e++) m = fmaxf(m, acc[e]);
        float Z = 0.f, p[NE];
#pragma unroll
        for (int e = 0; e < NE; e++) { p[e] = expf(acc[e] - m); Z += p[e]; }
        float invZ = 1.f / Z;
#pragma unroll
        for (int e = 0; e < NE; e++) atomicAdd(&g_usage[e], p[e] * invZ);
        // top-2 (lowest index wins ties, matching lax.top_k)
        int i0 = 0;
#pragma unroll
        for (int e = 1; e < NE; e++) if (acc[e] > acc[i0]) i0 = e;
        int i1 = (i0 == 0) ? 1 : 0;
#pragma unroll
        for (int e = 0; e < NE; e++) if (e != i0 && acc[e] > acc[i1]) i1 = e;
        float e1 = expf(acc[i1] - acc[i0]);
        float w0 = 1.f / (1.f + e1);
        float w1 = e1 * w0;
        g_topw[2 * warp]     = w0;
        g_topw[2 * warp + 1] = w1;
        int p0 = atomicAdd(&g_cnt[i0], 1);
        g_entry[i0 * T_TOK + p0] = warp * 2;
        int p1 = atomicAdd(&g_cnt[i1], 1);
        g_entry[i1 * T_TOK + p1] = warp * 2 + 1;
    }
}

// ---------------- aux loss ----------------
__global__ void aux_kernel(float* out, int has_aux) {
    if (!has_aux) return;
    float s = 0.f;
#pragma unroll
    for (int e = 0; e < NE; e++) { float u = g_usage[e] / (float)T_TOK; s += u * u; }
    out[(size_t)T_TOK * DIM] = (float)NE * s;
}

// ---------------- GEMM1+3 fused: H = silu(Xg@w1) * (Xg@w3)  ----------------
// BM=128 rows (gathered tokens), BN=64 hidden cols, BK=8. 256 thr, 8x4 microtile x2 accs.
__global__ __launch_bounds__(256) void gemm13_kernel(
    const float* __restrict__ x, const float* __restrict__ w1,
    const float* __restrict__ w3, int e)
{
    int n = g_cnt[e];
    int rowBase = blockIdx.y * 128;
    if (rowBase >= n) return;
    int colBase = blockIdx.x * 64;

    __shared__ float As[8][128];
    __shared__ float Bs1[8][64];
    __shared__ float Bs3[8][64];
    __shared__ int   toks[128];

    int tid = threadIdx.x;
    if (tid < 128) {
        int r = rowBase + tid;
        toks[tid] = (r < n) ? (g_entry[e * T_TOK + r] >> 1) : -1;
    }
    __syncthreads();

    const float* w1p = w1 + (size_t)e * DIM * HID + colBase;
    const float* w3p = w3 + (size_t)e * DIM * HID + colBase;

    int ty = tid >> 4, tx = tid & 15;
    int ar = tid >> 1, ak = (tid & 1) * 4;
    int bk = tid >> 5, bn = (tid & 31) * 2;
    int atok = toks[ar];
    const float* agp = (atok >= 0) ? (x + (size_t)atok * DIM + ak) : x;

    float acc1[8][4], acc3[8][4];
#pragma unroll
    for (int i = 0; i < 8; i++)
#pragma unroll
        for (int j = 0; j < 4; j++) { acc1[i][j] = 0.f; acc3[i][j] = 0.f; }

    for (int k0 = 0; k0 < DIM; k0 += 8) {
        float4 av = make_float4(0.f, 0.f, 0.f, 0.f);
        if (atok >= 0) av = *(const float4*)(agp + k0);
        As[ak + 0][ar] = av.x; As[ak + 1][ar] = av.y;
        As[ak + 2][ar] = av.z; As[ak + 3][ar] = av.w;
        float2 b1v = *(const float2*)(w1p + (size_t)(k0 + bk) * HID + bn);
        float2 b3v = *(const float2*)(w3p + (size_t)(k0 + bk) * HID + bn);
        Bs1[bk][bn] = b1v.x; Bs1[bk][bn + 1] = b1v.y;
        Bs3[bk][bn] = b3v.x; Bs3[bk][bn + 1] = b3v.y;
        __syncthreads();
#pragma unroll
        for (int kk = 0; kk < 8; kk++) {
            float a[8], b1[4], b3[4];
#pragma unroll
            for (int i = 0; i < 8; i++) a[i] = As[kk][ty * 8 + i];
#pragma unroll
            for (int j = 0; j < 4; j++) { b1[j] = Bs1[kk][tx * 4 + j]; b3[j] = Bs3[kk][tx * 4 + j]; }
#pragma unroll
            for (int i = 0; i < 8; i++)
#pragma unroll
                for (int j = 0; j < 4; j++) {
                    acc1[i][j] = fmaf(a[i], b1[j], acc1[i][j]);
                    acc3[i][j] = fmaf(a[i], b3[j], acc3[i][j]);
                }
        }
        __syncthreads();
    }

#pragma unroll
    for (int i = 0; i < 8; i++) {
        int r = rowBase + ty * 8 + i;
        if (r < n) {
            float4 hv;
            float* hvp = (float*)&hv;
#pragma unroll
            for (int j = 0; j < 4; j++) {
                float c1 = acc1[i][j];
                float sig = 1.f / (1.f + expf(-c1));
                hvp[j] = c1 * sig * acc3[i][j];
            }
            *(float4*)(&g_H[(size_t)r * HID + colBase + tx * 4]) = hv;
        }
    }
}

// ---------------- GEMM2: out[t] += w * (H @ w2)  ----------------
// BM=128, BN=128, BK=8. 256 thr, 8x8 microtile.
__global__ __launch_bounds__(256) void gemm2_kernel(
    const float* __restrict__ w2, float* __restrict__ out, int e)
{
    int n = g_cnt[e];
    int rowBase = blockIdx.y * 128;
    if (rowBase >= n) return;
    int colBase = blockIdx.x * 128;

    __shared__ float As[8][128];
    __shared__ float Bs[8][128];

    int tid = threadIdx.x;
    int ty = tid >> 4, tx = tid & 15;
    int ar = tid >> 1, ak = (tid & 1) * 4;
    int bk = tid >> 5, bn = (tid & 31) * 4;

    const float* w2p = w2 + (size_t)e * HID * DIM + colBase;
    bool arow_ok = (rowBase + ar) < n;
    const float* agp = g_H + (size_t)(rowBase + ar) * HID + ak;

    float acc[8][8];
#pragma unroll
    for (int i = 0; i < 8; i++)
#pragma unroll
        for (int j = 0; j < 8; j++) acc[i][j] = 0.f;

    for (int k0 = 0; k0 < HID; k0 += 8) {
        float4 av = make_float4(0.f, 0.f, 0.f, 0.f);
        if (arow_ok) av = *(const float4*)(agp + k0);
        As[ak + 0][ar] = av.x; As[ak + 1][ar] = av.y;
        As[ak + 2][ar] = av.z; As[ak + 3][ar] = av.w;
        float4 bv = *(const float4*)(w2p + (size_t)(k0 + bk) * DIM + bn);
        Bs[bk][bn] = bv.x; Bs[bk][bn + 1] = bv.y;
        Bs[bk][bn + 2] = bv.z; Bs[bk][bn + 3] = bv.w;
        __syncthreads();
#pragma unroll
        for (int kk = 0; kk < 8; kk++) {
            float a[8], b[8];
#pragma unroll
            for (int i = 0; i < 8; i++) a[i] = As[kk][ty * 8 + i];
#pragma unroll
            for (int j = 0; j < 8; j++) b[j] = Bs[kk][tx * 8 + j];
#pragma unroll
            for (int i = 0; i < 8; i++)
#pragma unroll
                for (int j = 0; j < 8; j++) acc[i][j] = fmaf(a[i], b[j], acc[i][j]);
        }
        __syncthreads();
    }

#pragma unroll
    for (int i = 0; i < 8; i++) {
        int r = rowBase + ty * 8 + i;
        if (r < n) {
            int slot = g_entry[e * T_TOK + r];
            float w = g_topw[slot];
            int t = slot >> 1;
            float* op = out + (size_t)t * DIM + colBase + tx * 8;
            float4 o0 = *(float4*)op;
            float4 o1 = *(float4*)(op + 4);
            o0.x += w * acc[i][0]; o0.y += w * acc[i][1];
            o0.z += w * acc[i][2]; o0.w += w * acc[i][3];
            o1.x += w * acc[i][4]; o1.y += w * acc[i][5];
            o1.z += w * acc[i][6]; o1.w += w * acc[i][7];
            *(float4*)op = o0;
            *(float4*)(op + 4) = o1;
        }
    }
}

extern "C" void kernel_launch(void* const* d_in, const int* in_sizes, int n_in,
                              void* d_out, int out_size) {
    const float* x  = (const float*)d_in[0];
    const float* gw = (const float*)d_in[1];
    const float* w1 = (const float*)d_in[2];
    const float* w2 = (const float*)d_in[3];
    const float* w3 = (const float*)d_in[4];
    float* out = (float*)d_out;

    const int out_elems = T_TOK * DIM;          // 8388608
    const int out_elems4 = out_elems / 4;

    init_kernel<<<(out_elems4 + 255) / 256, 256>>>(out, out_elems4);
    router_kernel<<<T_TOK / 8, 256>>>(x, gw);
    aux_kernel<<<1, 1>>>(out, (out_size > out_elems) ? 1 : 0);

    for (int e = 0; e < NE; e++) {
        gemm13_kernel<<<dim3(HID / 64, T_TOK / 128), 256>>>(x, w1, w3, e);
        gemm2_kernel<<<dim3(DIM / 128, T_TOK / 128), 256>>>(w2, out, e);
    }
}

// round 5
// speedup vs baseline: 2.0309x; 2.0309x over previous
#include <cuda_runtime.h>
#include <cuda_bf16.h>
#include <cstdint>
#include <math.h>

#define T_TOK 8192
#define DIM   1024
#define HID   4096
#define NE    8
#define KCH   32

// ------------------------- scratch (same set as passing R1) -------------------------
__device__ float g_H[(size_t)T_TOK * HID];   // hidden activations fp32
__device__ int   g_entry[NE * T_TOK];
__device__ float g_topw[2 * T_TOK];
__device__ int   g_cnt[NE];
__device__ float g_usage[NE];

// ------------------------- helpers -------------------------
__device__ __forceinline__ void mma16816(float* c, const uint32_t* a, const uint32_t* b) {
    asm volatile(
        "mma.sync.aligned.m16n8k16.row.col.f32.bf16.bf16.f32 "
        "{%0,%1,%2,%3}, {%4,%5,%6,%7}, {%8,%9}, {%0,%1,%2,%3};"
        : "+f"(c[0]), "+f"(c[1]), "+f"(c[2]), "+f"(c[3])
        : "r"(a[0]), "r"(a[1]), "r"(a[2]), "r"(a[3]), "r"(b[0]), "r"(b[1]));
}
__device__ __forceinline__ uint32_t pack_bf2(__nv_bfloat16 a, __nv_bfloat16 b) {
    return (uint32_t)__bfloat16_as_ushort(a) | ((uint32_t)__bfloat16_as_ushort(b) << 16);
}
// split two fp32 into hi/lo packed bf16x2
__device__ __forceinline__ void split2(float f0, float f1, uint32_t& hi, uint32_t& lo) {
    __nv_bfloat16 h0 = __float2bfloat16(f0);
    __nv_bfloat16 h1 = __float2bfloat16(f1);
    __nv_bfloat16 l0 = __float2bfloat16(f0 - __bfloat162float(h0));
    __nv_bfloat16 l1 = __float2bfloat16(f1 - __bfloat162float(h1));
    hi = pack_bf2(h0, h1);
    lo = pack_bf2(l0, l1);
}

// ------------------------- init / router / aux (verbatim from R1) -------------------------
__global__ void init_kernel(float* out, int out_elems4) {
    int i = blockIdx.x * blockDim.x + threadIdx.x;
    if (i < out_elems4) ((float4*)out)[i] = make_float4(0.f, 0.f, 0.f, 0.f);
    if (i < NE) { g_cnt[i] = 0; g_usage[i] = 0.f; }
}

__global__ void router_kernel(const float* __restrict__ x, const float* __restrict__ gw) {
    int warp = (blockIdx.x * blockDim.x + threadIdx.x) >> 5;
    int lane = threadIdx.x & 31;
    if (warp >= T_TOK) return;
    const float* xr = x + (size_t)warp * DIM;
    float acc[NE];
#pragma unroll
    for (int e = 0; e < NE; e++) acc[e] = 0.f;
    for (int d = lane; d < DIM; d += 32) {
        float xv = xr[d];
#pragma unroll
        for (int e = 0; e < NE; e++) acc[e] = fmaf(xv, gw[d * NE + e], acc[e]);
    }
#pragma unroll
    for (int off = 16; off; off >>= 1)
#pragma unroll
        for (int e = 0; e < NE; e++) acc[e] += __shfl_xor_sync(0xffffffffu, acc[e], off);
    if (lane == 0) {
        float m = acc[0];
#pragma unroll
        for (int e = 1; e < NE; e++) m = fmaxf(m, acc[e]);
        float Z = 0.f, p[NE];
#pragma unroll
        for (int e = 0; e < NE; e++) { p[e] = expf(acc[e] - m); Z += p[e]; }
        float invZ = 1.f / Z;
#pragma unroll
        for (int e = 0; e < NE; e++) atomicAdd(&g_usage[e], p[e] * invZ);
        int i0 = 0;
#pragma unroll
        for (int e = 1; e < NE; e++) if (acc[e] > acc[i0]) i0 = e;
        int i1 = (i0 == 0) ? 1 : 0;
#pragma unroll
        for (int e = 0; e < NE; e++) if (e != i0 && acc[e] > acc[i1]) i1 = e;
        float e1 = expf(acc[i1] - acc[i0]);
        float w0 = 1.f / (1.f + e1);
        g_topw[2 * warp]     = w0;
        g_topw[2 * warp + 1] = e1 * w0;
        int p0 = atomicAdd(&g_cnt[i0], 1);
        g_entry[i0 * T_TOK + p0] = warp * 2;
        int p1 = atomicAdd(&g_cnt[i1], 1);
        g_entry[i1 * T_TOK + p1] = warp * 2 + 1;
    }
}

__global__ void aux_kernel(float* out, int has_aux) {
    if (!has_aux) return;
    float s = 0.f;
#pragma unroll
    for (int e = 0; e < NE; e++) { float u = g_usage[e] / (float)T_TOK; s += u * u; }
    out[(size_t)T_TOK * DIM] = (float)NE * s;
}

// ------------------------- GEMM 1&3 (mma.sync, on-the-fly bf16 split) -------------------------
// CTA: M=64 tokens x N=64 hidden cols (both w1 & w3). K chunks of 32 over DIM.
// smem: padded [rows][18] u32 tiles, no swizzle. Fragments via direct LDS.
#define NCH13 (DIM / KCH)

__global__ __launch_bounds__(256)
void gemm13_mma_kernel(const float* __restrict__ x, const float* __restrict__ w1,
                       const float* __restrict__ w3, int e)
{
    __shared__ uint32_t sAh[64][18], sAl[64][18];
    __shared__ uint32_t sB1h[64][18], sB1l[64][18], sB3h[64][18], sB3l[64][18];
    __shared__ int sTok[64];

    int n = g_cnt[e];
    int rowBase = blockIdx.x * 64;       // token-block fastest -> weight-panel L2 reuse
    if (rowBase >= n) return;
    int colBase = blockIdx.y * 64;
    int tid = threadIdx.x, wid = tid >> 5, lane = tid & 31;
    int m0 = (wid & 3) * 16, n0 = (wid >> 2) * 32;
    int grp = lane >> 2, t4 = lane & 3;

    if (tid < 64) {
        int r = rowBase + tid;
        sTok[tid] = (r < n) ? (g_entry[e * T_TOK + r] >> 1) : 0;
    }
    __syncthreads();

    const size_t ebW = (size_t)e * DIM * HID;
    // A load coords: 2 float4 per thread
    int ar0 = tid >> 2, aseg0 = (tid & 3) * 2;            // rows 0..63, b32col base aseg0*? (4 floats = 2 b32)
    // Actually: 64 rows x 8 float4-segments = 512; idx = tid, tid+256
    int arA = tid >> 3,  asA = tid & 7;                   // first
    int arB = (tid + 256) >> 3, asB = (tid + 256) & 7;    // second
    (void)ar0; (void)aseg0;
    // B load coords: n = tid&63, kg = tid>>6 (4 groups of 8 k)
    int bn = tid & 63, bkg = tid >> 6;

    float4 avA, avB;
    float v1[8], v3[8];

    auto load_regs = [&](int c) {
        int k0 = c * KCH;
        avA = *(const float4*)(x + (size_t)sTok[arA] * DIM + k0 + asA * 4);
        avB = *(const float4*)(x + (size_t)sTok[arB] * DIM + k0 + asB * 4);
        const float* p1 = w1 + ebW + (size_t)(k0 + bkg * 8) * HID + colBase + bn;
        const float* p3 = w3 + ebW + (size_t)(k0 + bkg * 8) * HID + colBase + bn;
#pragma unroll
        for (int j = 0; j < 8; j++) { v1[j] = p1[(size_t)j * HID]; v3[j] = p3[(size_t)j * HID]; }
    };

    float c1[4][4], c3[4][4];
#pragma unroll
    for (int i = 0; i < 4; i++)
#pragma unroll
        for (int j = 0; j < 4; j++) { c1[i][j] = 0.f; c3[i][j] = 0.f; }

    load_regs(0);

    for (int c = 0; c < NCH13; c++) {
        __syncthreads();   // prior mma done with smem
        {
            uint32_t h, l;
            split2(avA.x, avA.y, h, l); sAh[arA][asA * 2] = h;     sAl[arA][asA * 2] = l;
            split2(avA.z, avA.w, h, l); sAh[arA][asA * 2 + 1] = h; sAl[arA][asA * 2 + 1] = l;
            split2(avB.x, avB.y, h, l); sAh[arB][asB * 2] = h;     sAl[arB][asB * 2] = l;
            split2(avB.z, avB.w, h, l); sAh[arB][asB * 2 + 1] = h; sAl[arB][asB * 2 + 1] = l;
#pragma unroll
            for (int p = 0; p < 4; p++) {
                split2(v1[2 * p], v1[2 * p + 1], h, l);
                sB1h[bn][bkg * 4 + p] = h; sB1l[bn][bkg * 4 + p] = l;
                split2(v3[2 * p], v3[2 * p + 1], h, l);
                sB3h[bn][bkg * 4 + p] = h; sB3l[bn][bkg * 4 + p] = l;
            }
        }
        __syncthreads();
        if (c + 1 < NCH13) load_regs(c + 1);   // overlap LDG with mma
#pragma unroll
        for (int ks = 0; ks < 2; ks++) {
            int cb = ks * 8 + t4;
            uint32_t ah[4], al[4];
            ah[0] = sAh[m0 + grp][cb];     al[0] = sAl[m0 + grp][cb];
            ah[1] = sAh[m0 + grp + 8][cb]; al[1] = sAl[m0 + grp + 8][cb];
            ah[2] = sAh[m0 + grp][cb + 4];     al[2] = sAl[m0 + grp][cb + 4];
            ah[3] = sAh[m0 + grp + 8][cb + 4]; al[3] = sAl[m0 + grp + 8][cb + 4];
#pragma unroll
            for (int nf = 0; nf < 4; nf++) {
                int nn = n0 + nf * 8 + grp;
                uint32_t b1h[2], b1l[2], b3h[2], b3l[2];
                b1h[0] = sB1h[nn][cb]; b1h[1] = sB1h[nn][cb + 4];
                b1l[0] = sB1l[nn][cb]; b1l[1] = sB1l[nn][cb + 4];
                b3h[0] = sB3h[nn][cb]; b3h[1] = sB3h[nn][cb + 4];
                b3l[0] = sB3l[nn][cb]; b3l[1] = sB3l[nn][cb + 4];
                mma16816(c1[nf], ah, b1h);
                mma16816(c1[nf], ah, b1l);
                mma16816(c1[nf], al, b1h);
                mma16816(c3[nf], ah, b3h);
                mma16816(c3[nf], ah, b3l);
                mma16816(c3[nf], al, b3h);
            }
        }
    }

    // epilogue: h = silu(c1) * c3 (fp32) -> g_H
#pragma unroll
    for (int nf = 0; nf < 4; nf++) {
        int col = colBase + n0 + nf * 8 + t4 * 2;
#pragma unroll
        for (int hf = 0; hf < 2; hf++) {
            int r = rowBase + m0 + grp + hf * 8;
            if (r < n) {
                float a0 = c1[nf][hf * 2 + 0], b0 = c3[nf][hf * 2 + 0];
                float a1 = c1[nf][hf * 2 + 1], b1 = c3[nf][hf * 2 + 1];
                float h0 = (a0 / (1.f + expf(-a0))) * b0;
                float h1 = (a1 / (1.f + expf(-a1))) * b1;
                *(float2*)(g_H + (size_t)r * HID + col) = make_float2(h0, h1);
            }
        }
    }
}

// ------------------------- GEMM 2 (mma.sync) -------------------------
// CTA: M=64 x N=128, K chunks of 32 over HID.
#define NCH2 (HID / KCH)

__global__ __launch_bounds__(256)
void gemm2_mma_kernel(const float* __restrict__ w2, float* __restrict__ out, int e)
{
    __shared__ uint32_t sAh[64][18], sAl[64][18];
    __shared__ uint32_t sBh[128][18], sBl[128][18];

    int n = g_cnt[e];
    int rowBase = blockIdx.x * 64;
    if (rowBase >= n) return;
    int colBase = blockIdx.y * 128;
    int tid = threadIdx.x, wid = tid >> 5, lane = tid & 31;
    int m0 = (wid & 3) * 16, n0 = (wid >> 2) * 64;
    int grp = lane >> 2, t4 = lane & 3;

    const size_t ebW = (size_t)e * HID * DIM;
    int arA = tid >> 3,  asA = tid & 7;
    int arB = (tid + 256) >> 3, asB = (tid + 256) & 7;
    int bn = tid & 127, bkg = tid >> 7;   // 2 groups of 16 k

    float4 avA, avB;
    float v2[16];

    auto load_regs = [&](int c) {
        int k0 = c * KCH;
        avA = *(const float4*)(g_H + (size_t)(rowBase + arA) * HID + k0 + asA * 4);
        avB = *(const float4*)(g_H + (size_t)(rowBase + arB) * HID + k0 + asB * 4);
        const float* p2 = w2 + ebW + (size_t)(k0 + bkg * 16) * DIM + colBase + bn;
#pragma unroll
        for (int j = 0; j < 16; j++) v2[j] = p2[(size_t)j * DIM];
    };

    float acc[8][4];
#pragma unroll
    for (int i = 0; i < 8; i++)
#pragma unroll
        for (int j = 0; j < 4; j++) acc[i][j] = 0.f;

    load_regs(0);

    for (int c = 0; c < NCH2; c++) {
        __syncthreads();
        {
            uint32_t h, l;
            split2(avA.x, avA.y, h, l); sAh[arA][asA * 2] = h;     sAl[arA][asA * 2] = l;
            split2(avA.z, avA.w, h, l); sAh[arA][asA * 2 + 1] = h; sAl[arA][asA * 2 + 1] = l;
            split2(avB.x, avB.y, h, l); sAh[arB][asB * 2] = h;     sAl[arB][asB * 2] = l;
            split2(avB.z, avB.w, h, l); sAh[arB][asB * 2 + 1] = h; sAl[arB][asB * 2 + 1] = l;
#pragma unroll
            for (int p = 0; p < 8; p++) {
                split2(v2[2 * p], v2[2 * p + 1], h, l);
                sBh[bn][bkg * 8 + p] = h; sBl[bn][bkg * 8 + p] = l;
            }
        }
        __syncthreads();
        if (c + 1 < NCH2) load_regs(c + 1);
#pragma unroll
        for (int ks = 0; ks < 2; ks++) {
            int cb = ks * 8 + t4;
            uint32_t ah[4], al[4];
            ah[0] = sAh[m0 + grp][cb];     al[0] = sAl[m0 + grp][cb];
            ah[1] = sAh[m0 + grp + 8][cb]; al[1] = sAl[m0 + grp + 8][cb];
            ah[2] = sAh[m0 + grp][cb + 4];     al[2] = sAl[m0 + grp][cb + 4];
            ah[3] = sAh[m0 + grp + 8][cb + 4]; al[3] = sAl[m0 + grp + 8][cb + 4];
#pragma unroll
            for (int nf = 0; nf < 8; nf++) {
                int nn = n0 + nf * 8 + grp;
                uint32_t bh[2], bl[2];
                bh[0] = sBh[nn][cb]; bh[1] = sBh[nn][cb + 4];
                bl[0] = sBl[nn][cb]; bl[1] = sBl[nn][cb + 4];
                mma16816(acc[nf], ah, bh);
                mma16816(acc[nf], ah, bl);
                mma16816(acc[nf], al, bh);
            }
        }
    }

    // epilogue: out[token] += wgt * acc
#pragma unroll
    for (int hf = 0; hf < 2; hf++) {
        int r = rowBase + m0 + grp + hf * 8;
        if (r < n) {
            int slot = g_entry[e * T_TOK + r];
            float wgt = g_topw[slot];
            size_t to = (size_t)(slot >> 1) * DIM;
#pragma unroll
            for (int nf = 0; nf < 8; nf++) {
                int col = colBase + n0 + nf * 8 + t4 * 2;
                float2 o = *(float2*)(out + to + col);
                o.x += wgt * acc[nf][hf * 2 + 0];
                o.y += wgt * acc[nf][hf * 2 + 1];
                *(float2*)(out + to + col) = o;
            }
        }
    }
}

// ------------------------- launch -------------------------
extern "C" void kernel_launch(void* const* d_in, const int* in_sizes, int n_in,
                              void* d_out, int out_size) {
    const float* x  = (const float*)d_in[0];
    const float* gw = (const float*)d_in[1];
    const float* w1 = (const float*)d_in[2];
    const float* w2 = (const float*)d_in[3];
    const float* w3 = (const float*)d_in[4];
    float* out = (float*)d_out;

    const int out_elems = T_TOK * DIM;
    const int out_elems4 = out_elems / 4;

    init_kernel<<<(out_elems4 + 255) / 256, 256>>>(out, out_elems4);
    router_kernel<<<T_TOK / 8, 256>>>(x, gw);
    aux_kernel<<<1, 1>>>(out, (out_size > out_elems) ? 1 : 0);

    for (int e = 0; e < NE; e++) {
        gemm13_mma_kernel<<<dim3(T_TOK / 64, HID / 64), 256>>>(x, w1, w3, e);
        gemm2_mma_kernel<<<dim3(T_TOK / 64, DIM / 128), 256>>>(w2, out, e);
    }
}

// round 6
// speedup vs baseline: 2.3122x; 1.1385x over previous
#include <cuda_runtime.h>
#include <cuda_bf16.h>
#include <cstdint>
#include <math.h>

#define T_TOK 8192
#define DIM   1024
#define HID   4096
#define NE    8
#define KCH   32
#define PAD   20   // u32 stride per row: conflict-free ldmatrix (20*i mod 32 distinct, spacing 4)

// ------------------------- scratch -------------------------
__device__ float g_H[(size_t)T_TOK * HID];
__device__ int   g_entry[NE * T_TOK];
__device__ float g_topw[2 * T_TOK];
__device__ int   g_cnt[NE];
__device__ float g_usage[NE];

// ------------------------- helpers -------------------------
__device__ __forceinline__ uint32_t smem_to_u32(const void* p) {
    uint32_t a;
    asm("{ .reg .u64 t; cvta.to.shared.u64 t, %1; cvt.u32.u64 %0, t; }" : "=r"(a) : "l"(p));
    return a;
}
__device__ __forceinline__ void ldm_x4(uint32_t* f, uint32_t addr) {
    asm volatile("ldmatrix.sync.aligned.m8n8.x4.shared.b16 {%0,%1,%2,%3}, [%4];"
        : "=r"(f[0]), "=r"(f[1]), "=r"(f[2]), "=r"(f[3]) : "r"(addr));
}
// lane address into padded [rows][PAD] u32 tile for x4 covering rows[row0,row0+16) x k16 step ks
__device__ __forceinline__ uint32_t ldm_addr(uint32_t base, int lane, int row0, int ks) {
    int r = row0 + (lane & 7) + ((lane >> 3) & 1) * 8;
    int c = ks * 8 + (lane >> 4) * 4;
    return base + (uint32_t)(r * PAD + c) * 4u;
}
__device__ __forceinline__ void mma16816(float* c, const uint32_t* a, const uint32_t* b) {
    asm volatile(
        "mma.sync.aligned.m16n8k16.row.col.f32.bf16.bf16.f32 "
        "{%0,%1,%2,%3}, {%4,%5,%6,%7}, {%8,%9}, {%0,%1,%2,%3};"
        : "+f"(c[0]), "+f"(c[1]), "+f"(c[2]), "+f"(c[3])
        : "r"(a[0]), "r"(a[1]), "r"(a[2]), "r"(a[3]), "r"(b[0]), "r"(b[1]));
}
__device__ __forceinline__ uint32_t pack_bf2(__nv_bfloat16 a, __nv_bfloat16 b) {
    return (uint32_t)__bfloat16_as_ushort(a) | ((uint32_t)__bfloat16_as_ushort(b) << 16);
}
__device__ __forceinline__ void split2(float f0, float f1, uint32_t& hi, uint32_t& lo) {
    __nv_bfloat16 h0 = __float2bfloat16(f0);
    __nv_bfloat16 h1 = __float2bfloat16(f1);
    __nv_bfloat16 l0 = __float2bfloat16(f0 - __bfloat162float(h0));
    __nv_bfloat16 l1 = __float2bfloat16(f1 - __bfloat162float(h1));
    hi = pack_bf2(h0, h1);
    lo = pack_bf2(l0, l1);
}

// ------------------------- init / router / aux -------------------------
__global__ void init_kernel(float* out, int out_elems4) {
    int i = blockIdx.x * blockDim.x + threadIdx.x;
    if (i < out_elems4) ((float4*)out)[i] = make_float4(0.f, 0.f, 0.f, 0.f);
    if (i < NE) { g_cnt[i] = 0; g_usage[i] = 0.f; }
}

__global__ void router_kernel(const float* __restrict__ x, const float* __restrict__ gw) {
    int warp = (blockIdx.x * blockDim.x + threadIdx.x) >> 5;
    int lane = threadIdx.x & 31;
    if (warp >= T_TOK) return;
    const float* xr = x + (size_t)warp * DIM;
    float acc[NE];
#pragma unroll
    for (int e = 0; e < NE; e++) acc[e] = 0.f;
    for (int d = lane; d < DIM; d += 32) {
        float xv = xr[d];
#pragma unroll
        for (int e = 0; e < NE; e++) acc[e] = fmaf(xv, gw[d * NE + e], acc[e]);
    }
#pragma unroll
    for (int off = 16; off; off >>= 1)
#pragma unroll
        for (int e = 0; e < NE; e++) acc[e] += __shfl_xor_sync(0xffffffffu, acc[e], off);
    if (lane == 0) {
        float m = acc[0];
#pragma unroll
        for (int e = 1; e < NE; e++) m = fmaxf(m, acc[e]);
        float Z = 0.f, p[NE];
#pragma unroll
        for (int e = 0; e < NE; e++) { p[e] = expf(acc[e] - m); Z += p[e]; }
        float invZ = 1.f / Z;
#pragma unroll
        for (int e = 0; e < NE; e++) atomicAdd(&g_usage[e], p[e] * invZ);
        int i0 = 0;
#pragma unroll
        for (int e = 1; e < NE; e++) if (acc[e] > acc[i0]) i0 = e;
        int i1 = (i0 == 0) ? 1 : 0;
#pragma unroll
        for (int e = 0; e < NE; e++) if (e != i0 && acc[e] > acc[i1]) i1 = e;
        float e1 = expf(acc[i1] - acc[i0]);
        float w0 = 1.f / (1.f + e1);
        g_topw[2 * warp]     = w0;
        g_topw[2 * warp + 1] = e1 * w0;
        int p0 = atomicAdd(&g_cnt[i0], 1);
        g_entry[i0 * T_TOK + p0] = warp * 2;
        int p1 = atomicAdd(&g_cnt[i1], 1);
        g_entry[i1 * T_TOK + p1] = warp * 2 + 1;
    }
}

__global__ void aux_kernel(float* out, int has_aux) {
    if (!has_aux) return;
    float s = 0.f;
#pragma unroll
    for (int e = 0; e < NE; e++) { float u = g_usage[e] / (float)T_TOK; s += u * u; }
    out[(size_t)T_TOK * DIM] = (float)NE * s;
}

// ------------------------- GEMM 1&3 -------------------------
#define NCH13 (DIM / KCH)

__global__ __launch_bounds__(256)
void gemm13_mma_kernel(const float* __restrict__ x, const float* __restrict__ w1,
                       const float* __restrict__ w3, int e)
{
    __shared__ uint32_t sAh[64][PAD], sAl[64][PAD];
    __shared__ uint32_t sB1h[64][PAD], sB1l[64][PAD], sB3h[64][PAD], sB3l[64][PAD];
    __shared__ int sTok[64];

    int n = g_cnt[e];
    int rowBase = blockIdx.x * 64;
    if (rowBase >= n) return;
    int colBase = blockIdx.y * 64;
    int tid = threadIdx.x, wid = tid >> 5, lane = tid & 31;
    int m0 = (wid & 3) * 16, n0 = (wid >> 2) * 32;
    int grp = lane >> 2, t4 = lane & 3;

    if (tid < 64) {
        int r = rowBase + tid;
        sTok[tid] = (r < n) ? (g_entry[e * T_TOK + r] >> 1) : 0;
    }
    __syncthreads();

    const uint32_t bAh = smem_to_u32(sAh), bAl = smem_to_u32(sAl);
    const uint32_t b1hB = smem_to_u32(sB1h), b1lB = smem_to_u32(sB1l);
    const uint32_t b3hB = smem_to_u32(sB3h), b3lB = smem_to_u32(sB3l);

    const size_t ebW = (size_t)e * DIM * HID;
    int arA = tid >> 3,  asA = tid & 7;
    int arB = (tid + 256) >> 3, asB = (tid + 256) & 7;
    int bn = tid & 63, bkg = tid >> 6;

    float4 avA, avB;
    float v1[8], v3[8];

    auto load_regs = [&](int c) {
        int k0 = c * KCH;
        avA = *(const float4*)(x + (size_t)sTok[arA] * DIM + k0 + asA * 4);
        avB = *(const float4*)(x + (size_t)sTok[arB] * DIM + k0 + asB * 4);
        const float* p1 = w1 + ebW + (size_t)(k0 + bkg * 8) * HID + colBase + bn;
        const float* p3 = w3 + ebW + (size_t)(k0 + bkg * 8) * HID + colBase + bn;
#pragma unroll
        for (int j = 0; j < 8; j++) { v1[j] = p1[(size_t)j * HID]; v3[j] = p3[(size_t)j * HID]; }
    };

    float c1[4][4], c3[4][4];
#pragma unroll
    for (int i = 0; i < 4; i++)
#pragma unroll
        for (int j = 0; j < 4; j++) { c1[i][j] = 0.f; c3[i][j] = 0.f; }

    load_regs(0);

    for (int c = 0; c < NCH13; c++) {
        __syncthreads();
        {
            uint32_t h, l;
            split2(avA.x, avA.y, h, l); sAh[arA][asA * 2] = h;     sAl[arA][asA * 2] = l;
            split2(avA.z, avA.w, h, l); sAh[arA][asA * 2 + 1] = h; sAl[arA][asA * 2 + 1] = l;
            split2(avB.x, avB.y, h, l); sAh[arB][asB * 2] = h;     sAl[arB][asB * 2] = l;
            split2(avB.z, avB.w, h, l); sAh[arB][asB * 2 + 1] = h; sAl[arB][asB * 2 + 1] = l;
#pragma unroll
            for (int p = 0; p < 4; p++) {
                split2(v1[2 * p], v1[2 * p + 1], h, l);
                sB1h[bn][bkg * 4 + p] = h; sB1l[bn][bkg * 4 + p] = l;
                split2(v3[2 * p], v3[2 * p + 1], h, l);
                sB3h[bn][bkg * 4 + p] = h; sB3l[bn][bkg * 4 + p] = l;
            }
        }
        __syncthreads();
        if (c + 1 < NCH13) load_regs(c + 1);
#pragma unroll
        for (int ks = 0; ks < 2; ks++) {
            uint32_t ah[4], al[4];
            ldm_x4(ah, ldm_addr(bAh, lane, m0, ks));
            ldm_x4(al, ldm_addr(bAl, lane, m0, ks));
#pragma unroll
            for (int g = 0; g < 2; g++) {
                uint32_t f1h[4], f1l[4], f3h[4], f3l[4];
                ldm_x4(f1h, ldm_addr(b1hB, lane, n0 + g * 16, ks));
                ldm_x4(f1l, ldm_addr(b1lB, lane, n0 + g * 16, ks));
                ldm_x4(f3h, ldm_addr(b3hB, lane, n0 + g * 16, ks));
                ldm_x4(f3l, ldm_addr(b3lB, lane, n0 + g * 16, ks));
#pragma unroll
                for (int h2 = 0; h2 < 2; h2++) {
                    int nt = g * 2 + h2;
                    uint32_t b1hF[2] = { f1h[h2], f1h[h2 + 2] };
                    uint32_t b1lF[2] = { f1l[h2], f1l[h2 + 2] };
                    uint32_t b3hF[2] = { f3h[h2], f3h[h2 + 2] };
                    uint32_t b3lF[2] = { f3l[h2], f3l[h2 + 2] };
                    mma16816(c1[nt], ah, b1hF);
                    mma16816(c1[nt], ah, b1lF);
                    mma16816(c1[nt], al, b1hF);
                    mma16816(c3[nt], ah, b3hF);
                    mma16816(c3[nt], ah, b3lF);
                    mma16816(c3[nt], al, b3hF);
                }
            }
        }
    }

    // epilogue: h = silu(c1) * c3 -> g_H
#pragma unroll
    for (int nt = 0; nt < 4; nt++) {
        int col = colBase + n0 + nt * 8 + t4 * 2;
#pragma unroll
        for (int hf = 0; hf < 2; hf++) {
            int r = rowBase + m0 + grp + hf * 8;
            if (r < n) {
                float a0 = c1[nt][hf * 2 + 0], b0 = c3[nt][hf * 2 + 0];
                float a1 = c1[nt][hf * 2 + 1], b1 = c3[nt][hf * 2 + 1];
                float h0 = (a0 / (1.f + expf(-a0))) * b0;
                float h1 = (a1 / (1.f + expf(-a1))) * b1;
                *(float2*)(g_H + (size_t)r * HID + col) = make_float2(h0, h1);
            }
        }
    }
}

// ------------------------- GEMM 2 -------------------------
#define NCH2 (HID / KCH)

__global__ __launch_bounds__(256)
void gemm2_mma_kernel(const float* __restrict__ w2, float* __restrict__ out, int e)
{
    __shared__ uint32_t sAh[64][PAD], sAl[64][PAD];
    __shared__ uint32_t sBh[128][PAD], sBl[128][PAD];

    int n = g_cnt[e];
    int rowBase = blockIdx.x * 64;
    if (rowBase >= n) return;
    int colBase = blockIdx.y * 128;
    int tid = threadIdx.x, wid = tid >> 5, lane = tid & 31;
    int m0 = (wid & 3) * 16, n0 = (wid >> 2) * 64;
    int grp = lane >> 2, t4 = lane & 3;

    const uint32_t bAh = smem_to_u32(sAh), bAl = smem_to_u32(sAl);
    const uint32_t bBh = smem_to_u32(sBh), bBl = smem_to_u32(sBl);

    const size_t ebW = (size_t)e * HID * DIM;
    int arA = tid >> 3,  asA = tid & 7;
    int arB = (tid + 256) >> 3, asB = (tid + 256) & 7;
    int bn = tid & 127, bkg = tid >> 7;

    float4 avA, avB;
    float v2[16];

    auto load_regs = [&](int c) {
        int k0 = c * KCH;
        avA = *(const float4*)(g_H + (size_t)(rowBase + arA) * HID + k0 + asA * 4);
        avB = *(const float4*)(g_H + (size_t)(rowBase + arB) * HID + k0 + asB * 4);
        const float* p2 = w2 + ebW + (size_t)(k0 + bkg * 16) * DIM + colBase + bn;
#pragma unroll
        for (int j = 0; j < 16; j++) v2[j] = p2[(size_t)j * DIM];
    };

    float acc[8][4];
#pragma unroll
    for (int i = 0; i < 8; i++)
#pragma unroll
        for (int j = 0; j < 4; j++) acc[i][j] = 0.f;

    load_regs(0);

    for (int c = 0; c < NCH2; c++) {
        __syncthreads();
        {
            uint32_t h, l;
            split2(avA.x, avA.y, h, l); sAh[arA][asA * 2] = h;     sAl[arA][asA * 2] = l;
            split2(avA.z, avA.w, h, l); sAh[arA][asA * 2 + 1] = h; sAl[arA][asA * 2 + 1] = l;
            split2(avB.x, avB.y, h, l); sAh[arB][asB * 2] = h;     sAl[arB][asB * 2] = l;
            split2(avB.z, avB.w, h, l); sAh[arB][asB * 2 + 1] = h; sAl[arB][asB * 2 + 1] = l;
#pragma unroll
            for (int p = 0; p < 8; p++) {
                split2(v2[2 * p], v2[2 * p + 1], h, l);
                sBh[bn][bkg * 8 + p] = h; sBl[bn][bkg * 8 + p] = l;
            }
        }
        __syncthreads();
        if (c + 1 < NCH2) load_regs(c + 1);
#pragma unroll
        for (int ks = 0; ks < 2; ks++) {
            uint32_t ah[4], al[4];
            ldm_x4(ah, ldm_addr(bAh, lane, m0, ks));
            ldm_x4(al, ldm_addr(bAl, lane, m0, ks));
#pragma unroll
            for (int g = 0; g < 4; g++) {
                uint32_t fh[4], fl[4];
                ldm_x4(fh, ldm_addr(bBh, lane, n0 + g * 16, ks));
                ldm_x4(fl, ldm_addr(bBl, lane, n0 + g * 16, ks));
#pragma unroll
                for (int h2 = 0; h2 < 2; h2++) {
                    int nt = g * 2 + h2;
                    uint32_t bhF[2] = { fh[h2], fh[h2 + 2] };
                    uint32_t blF[2] = { fl[h2], fl[h2 + 2] };
                    mma16816(acc[nt], ah, bhF);
                    mma16816(acc[nt], ah, blF);
                    mma16816(acc[nt], al, bhF);
                }
            }
        }
    }

    // epilogue
#pragma unroll
    for (int hf = 0; hf < 2; hf++) {
        int r = rowBase + m0 + grp + hf * 8;
        if (r < n) {
            int slot = g_entry[e * T_TOK + r];
            float wgt = g_topw[slot];
            size_t to = (size_t)(slot >> 1) * DIM;
#pragma unroll
            for (int nt = 0; nt < 8; nt++) {
                int col = colBase + n0 + nt * 8 + t4 * 2;
                float2 o = *(float2*)(out + to + col);
                o.x += wgt * acc[nt][hf * 2 + 0];
                o.y += wgt * acc[nt][hf * 2 + 1];
                *(float2*)(out + to + col) = o;
            }
        }
    }
}

// ------------------------- launch -------------------------
extern "C" void kernel_launch(void* const* d_in, const int* in_sizes, int n_in,
                              void* d_out, int out_size) {
    const float* x  = (const float*)d_in[0];
    const float* gw = (const float*)d_in[1];
    const float* w1 = (const float*)d_in[2];
    const float* w2 = (const float*)d_in[3];
    const float* w3 = (const float*)d_in[4];
    float* out = (float*)d_out;

    const int out_elems = T_TOK * DIM;
    const int out_elems4 = out_elems / 4;

    init_kernel<<<(out_elems4 + 255) / 256, 256>>>(out, out_elems4);
    router_kernel<<<T_TOK / 8, 256>>>(x, gw);
    aux_kernel<<<1, 1>>>(out, (out_size > out_elems) ? 1 : 0);

    for (int e = 0; e < NE; e++) {
        gemm13_mma_kernel<<<dim3(T_TOK / 64, HID / 64), 256>>>(x, w1, w3, e);
        gemm2_mma_kernel<<<dim3(T_TOK / 64, DIM / 128), 256>>>(w2, out, e);
    }
}

// round 7
// speedup vs baseline: 2.3593x; 1.0204x over previous
#include <cuda_runtime.h>
#include <cuda_bf16.h>
#include <cstdint>
#include <math.h>

#define T_TOK 8192
#define DIM   1024
#define HID   4096
#define NE    8
#define KCH   32
#define PAD   20   // u32 row stride: conflict-free ldmatrix

// ------------------------- scratch -------------------------
__device__ float g_H[(size_t)T_TOK * HID];
__device__ int   g_entry[NE * T_TOK];
__device__ float g_topw[2 * T_TOK];
__device__ int   g_cnt[NE];
__device__ float g_usage[NE];

// ------------------------- helpers -------------------------
__device__ __forceinline__ uint32_t smem_to_u32(const void* p) {
    uint32_t a;
    asm("{ .reg .u64 t; cvta.to.shared.u64 t, %1; cvt.u32.u64 %0, t; }" : "=r"(a) : "l"(p));
    return a;
}
__device__ __forceinline__ void ldm_x4(uint32_t* f, uint32_t addr) {
    asm volatile("ldmatrix.sync.aligned.m8n8.x4.shared.b16 {%0,%1,%2,%3}, [%4];"
        : "=r"(f[0]), "=r"(f[1]), "=r"(f[2]), "=r"(f[3]) : "r"(addr));
}
__device__ __forceinline__ uint32_t ldm_addr(uint32_t base, int lane, int row0, int ks) {
    int r = row0 + (lane & 7) + ((lane >> 3) & 1) * 8;
    int c = ks * 8 + (lane >> 4) * 4;
    return base + (uint32_t)(r * PAD + c) * 4u;
}
__device__ __forceinline__ void mma16816(float* c, const uint32_t* a, const uint32_t* b) {
    asm volatile(
        "mma.sync.aligned.m16n8k16.row.col.f32.bf16.bf16.f32 "
        "{%0,%1,%2,%3}, {%4,%5,%6,%7}, {%8,%9}, {%0,%1,%2,%3};"
        : "+f"(c[0]), "+f"(c[1]), "+f"(c[2]), "+f"(c[3])
        : "r"(a[0]), "r"(a[1]), "r"(a[2]), "r"(a[3]), "r"(b[0]), "r"(b[1]));
}
__device__ __forceinline__ uint32_t pack_bf2(__nv_bfloat16 a, __nv_bfloat16 b) {
    return (uint32_t)__bfloat16_as_ushort(a) | ((uint32_t)__bfloat16_as_ushort(b) << 16);
}
__device__ __forceinline__ void split2(float f0, float f1, uint32_t& hi, uint32_t& lo) {
    __nv_bfloat16 h0 = __float2bfloat16(f0);
    __nv_bfloat16 h1 = __float2bfloat16(f1);
    __nv_bfloat16 l0 = __float2bfloat16(f0 - __bfloat162float(h0));
    __nv_bfloat16 l1 = __float2bfloat16(f1 - __bfloat162float(h1));
    hi = pack_bf2(h0, h1);
    lo = pack_bf2(l0, l1);
}

// ------------------------- init / router / aux -------------------------
__global__ void init_kernel(float* out, int out_elems4) {
    int i = blockIdx.x * blockDim.x + threadIdx.x;
    if (i < out_elems4) ((float4*)out)[i] = make_float4(0.f, 0.f, 0.f, 0.f);
    if (i < NE) { g_cnt[i] = 0; g_usage[i] = 0.f; }
}

__global__ void router_kernel(const float* __restrict__ x, const float* __restrict__ gw) {
    int warp = (blockIdx.x * blockDim.x + threadIdx.x) >> 5;
    int lane = threadIdx.x & 31;
    if (warp >= T_TOK) return;
    const float* xr = x + (size_t)warp * DIM;
    float acc[NE];
#pragma unroll
    for (int e = 0; e < NE; e++) acc[e] = 0.f;
    for (int d = lane; d < DIM; d += 32) {
        float xv = xr[d];
#pragma unroll
        for (int e = 0; e < NE; e++) acc[e] = fmaf(xv, gw[d * NE + e], acc[e]);
    }
#pragma unroll
    for (int off = 16; off; off >>= 1)
#pragma unroll
        for (int e = 0; e < NE; e++) acc[e] += __shfl_xor_sync(0xffffffffu, acc[e], off);
    if (lane == 0) {
        float m = acc[0];
#pragma unroll
        for (int e = 1; e < NE; e++) m = fmaxf(m, acc[e]);
        float Z = 0.f, p[NE];
#pragma unroll
        for (int e = 0; e < NE; e++) { p[e] = expf(acc[e] - m); Z += p[e]; }
        float invZ = 1.f / Z;
#pragma unroll
        for (int e = 0; e < NE; e++) atomicAdd(&g_usage[e], p[e] * invZ);
        int i0 = 0;
#pragma unroll
        for (int e = 1; e < NE; e++) if (acc[e] > acc[i0]) i0 = e;
        int i1 = (i0 == 0) ? 1 : 0;
#pragma unroll
        for (int e = 0; e < NE; e++) if (e != i0 && acc[e] > acc[i1]) i1 = e;
        float e1 = expf(acc[i1] - acc[i0]);
        float w0 = 1.f / (1.f + e1);
        g_topw[2 * warp]     = w0;
        g_topw[2 * warp + 1] = e1 * w0;
        int p0 = atomicAdd(&g_cnt[i0], 1);
        g_entry[i0 * T_TOK + p0] = warp * 2;
        int p1 = atomicAdd(&g_cnt[i1], 1);
        g_entry[i1 * T_TOK + p1] = warp * 2 + 1;
    }
}

__global__ void aux_kernel(float* out, int has_aux) {
    if (!has_aux) return;
    float s = 0.f;
#pragma unroll
    for (int e = 0; e < NE; e++) { float u = g_usage[e] / (float)T_TOK; s += u * u; }
    out[(size_t)T_TOK * DIM] = (float)NE * s;
}

// ------------------------- GEMM 1&3: CTA 128x64, warp m32n32 -------------------------
#define NCH13 (DIM / KCH)

__global__ __launch_bounds__(256)
void gemm13_mma_kernel(const float* __restrict__ x, const float* __restrict__ w1,
                       const float* __restrict__ w3, int e)
{
    __shared__ uint32_t sAh[128][PAD], sAl[128][PAD];
    __shared__ uint32_t sB1h[64][PAD], sB1l[64][PAD], sB3h[64][PAD], sB3l[64][PAD];
    __shared__ int sTok[128];

    int n = g_cnt[e];
    int rowBase = blockIdx.x * 128;
    if (rowBase >= n) return;
    int colBase = blockIdx.y * 64;
    int tid = threadIdx.x, wid = tid >> 5, lane = tid & 31;
    int m0 = (wid & 3) * 32, n0 = (wid >> 2) * 32;
    int grp = lane >> 2, t4 = lane & 3;

    if (tid < 128) {
        int r = rowBase + tid;
        sTok[tid] = (r < n) ? (g_entry[e * T_TOK + r] >> 1) : 0;
    }
    __syncthreads();

    const uint32_t bAh = smem_to_u32(sAh), bAl = smem_to_u32(sAl);
    const uint32_t b1hB = smem_to_u32(sB1h), b1lB = smem_to_u32(sB1l);
    const uint32_t b3hB = smem_to_u32(sB3h), b3lB = smem_to_u32(sB3l);

    const size_t ebW = (size_t)e * DIM * HID;
    // A: 4 float4 per thread (128 rows x 8 segs)
    int arow[4], aseg[4];
#pragma unroll
    for (int t = 0; t < 4; t++) { int idx = tid + t * 256; arow[t] = idx >> 3; aseg[t] = idx & 7; }
    // B: 8 strided floats per matrix
    int bn = tid & 63, bkg = tid >> 6;

    float4 av[4];
    float v1[8], v3[8];

    auto load_regs = [&](int c) {
        int k0 = c * KCH;
#pragma unroll
        for (int t = 0; t < 4; t++)
            av[t] = *(const float4*)(x + (size_t)sTok[arow[t]] * DIM + k0 + aseg[t] * 4);
        const float* p1 = w1 + ebW + (size_t)(k0 + bkg * 8) * HID + colBase + bn;
        const float* p3 = w3 + ebW + (size_t)(k0 + bkg * 8) * HID + colBase + bn;
#pragma unroll
        for (int j = 0; j < 8; j++) { v1[j] = p1[(size_t)j * HID]; v3[j] = p3[(size_t)j * HID]; }
    };

    float c1[2][4][4], c3[2][4][4];
#pragma unroll
    for (int mt = 0; mt < 2; mt++)
#pragma unroll
        for (int j = 0; j < 4; j++)
#pragma unroll
            for (int q = 0; q < 4; q++) { c1[mt][j][q] = 0.f; c3[mt][j][q] = 0.f; }

    load_regs(0);

    for (int c = 0; c < NCH13; c++) {
        __syncthreads();
        {
            uint32_t h, l;
#pragma unroll
            for (int t = 0; t < 4; t++) {
                split2(av[t].x, av[t].y, h, l);
                sAh[arow[t]][aseg[t] * 2] = h;     sAl[arow[t]][aseg[t] * 2] = l;
                split2(av[t].z, av[t].w, h, l);
                sAh[arow[t]][aseg[t] * 2 + 1] = h; sAl[arow[t]][aseg[t] * 2 + 1] = l;
            }
#pragma unroll
            for (int p = 0; p < 4; p++) {
                split2(v1[2 * p], v1[2 * p + 1], h, l);
                sB1h[bn][bkg * 4 + p] = h; sB1l[bn][bkg * 4 + p] = l;
                split2(v3[2 * p], v3[2 * p + 1], h, l);
                sB3h[bn][bkg * 4 + p] = h; sB3l[bn][bkg * 4 + p] = l;
            }
        }
        __syncthreads();
        if (c + 1 < NCH13) load_regs(c + 1);
#pragma unroll
        for (int ks = 0; ks < 2; ks++) {
            uint32_t ah[2][4], al[2][4];
#pragma unroll
            for (int mt = 0; mt < 2; mt++) {
                ldm_x4(ah[mt], ldm_addr(bAh, lane, m0 + mt * 16, ks));
                ldm_x4(al[mt], ldm_addr(bAl, lane, m0 + mt * 16, ks));
            }
#pragma unroll
            for (int g = 0; g < 2; g++) {
                uint32_t f1h[4], f1l[4], f3h[4], f3l[4];
                ldm_x4(f1h, ldm_addr(b1hB, lane, n0 + g * 16, ks));
                ldm_x4(f1l, ldm_addr(b1lB, lane, n0 + g * 16, ks));
                ldm_x4(f3h, ldm_addr(b3hB, lane, n0 + g * 16, ks));
                ldm_x4(f3l, ldm_addr(b3lB, lane, n0 + g * 16, ks));
#pragma unroll
                for (int h2 = 0; h2 < 2; h2++) {
                    int nt = g * 2 + h2;
                    uint32_t b1hF[2] = { f1h[h2], f1h[h2 + 2] };
                    uint32_t b1lF[2] = { f1l[h2], f1l[h2 + 2] };
                    uint32_t b3hF[2] = { f3h[h2], f3h[h2 + 2] };
                    uint32_t b3lF[2] = { f3l[h2], f3l[h2 + 2] };
#pragma unroll
                    for (int mt = 0; mt < 2; mt++) {
                        mma16816(c1[mt][nt], ah[mt], b1hF);
                        mma16816(c1[mt][nt], ah[mt], b1lF);
                        mma16816(c1[mt][nt], al[mt], b1hF);
                        mma16816(c3[mt][nt], ah[mt], b3hF);
                        mma16816(c3[mt][nt], ah[mt], b3lF);
                        mma16816(c3[mt][nt], al[mt], b3hF);
                    }
                }
            }
        }
    }

    // epilogue: h = silu(c1) * c3 -> g_H
#pragma unroll
    for (int mt = 0; mt < 2; mt++)
#pragma unroll
        for (int nt = 0; nt < 4; nt++) {
            int col = colBase + n0 + nt * 8 + t4 * 2;
#pragma unroll
            for (int hf = 0; hf < 2; hf++) {
                int r = rowBase + m0 + mt * 16 + grp + hf * 8;
                if (r < n) {
                    float a0 = c1[mt][nt][hf * 2 + 0], b0 = c3[mt][nt][hf * 2 + 0];
                    float a1 = c1[mt][nt][hf * 2 + 1], b1 = c3[mt][nt][hf * 2 + 1];
                    float h0 = (a0 / (1.f + expf(-a0))) * b0;
                    float h1 = (a1 / (1.f + expf(-a1))) * b1;
                    *(float2*)(g_H + (size_t)r * HID + col) = make_float2(h0, h1);
                }
            }
        }
}

// ------------------------- GEMM 2: CTA 128x64, warp m32n32 -------------------------
#define NCH2 (HID / KCH)

__global__ __launch_bounds__(256)
void gemm2_mma_kernel(const float* __restrict__ w2, float* __restrict__ out, int e)
{
    __shared__ uint32_t sAh[128][PAD], sAl[128][PAD];
    __shared__ uint32_t sBh[64][PAD], sBl[64][PAD];

    int n = g_cnt[e];
    int rowBase = blockIdx.x * 128;
    if (rowBase >= n) return;
    int colBase = blockIdx.y * 64;
    int tid = threadIdx.x, wid = tid >> 5, lane = tid & 31;
    int m0 = (wid & 3) * 32, n0 = (wid >> 2) * 32;
    int grp = lane >> 2, t4 = lane & 3;

    const uint32_t bAh = smem_to_u32(sAh), bAl = smem_to_u32(sAl);
    const uint32_t bBh = smem_to_u32(sBh), bBl = smem_to_u32(sBl);

    const size_t ebW = (size_t)e * HID * DIM;
    int arow[4], aseg[4];
#pragma unroll
    for (int t = 0; t < 4; t++) { int idx = tid + t * 256; arow[t] = idx >> 3; aseg[t] = idx & 7; }
    int bn = tid & 63, bkg = tid >> 6;

    float4 av[4];
    float v2[8];

    auto load_regs = [&](int c) {
        int k0 = c * KCH;
#pragma unroll
        for (int t = 0; t < 4; t++) {
            int r = rowBase + arow[t];
            if (r >= T_TOK) r = T_TOK - 1;
            av[t] = *(const float4*)(g_H + (size_t)r * HID + k0 + aseg[t] * 4);
        }
        const float* p2 = w2 + ebW + (size_t)(k0 + bkg * 8) * DIM + colBase + bn;
#pragma unroll
        for (int j = 0; j < 8; j++) v2[j] = p2[(size_t)j * DIM];
    };

    float acc[2][4][4];
#pragma unroll
    for (int mt = 0; mt < 2; mt++)
#pragma unroll
        for (int j = 0; j < 4; j++)
#pragma unroll
            for (int q = 0; q < 4; q++) acc[mt][j][q] = 0.f;

    load_regs(0);

    for (int c = 0; c < NCH2; c++) {
        __syncthreads();
        {
            uint32_t h, l;
#pragma unroll
            for (int t = 0; t < 4; t++) {
                split2(av[t].x, av[t].y, h, l);
                sAh[arow[t]][aseg[t] * 2] = h;     sAl[arow[t]][aseg[t] * 2] = l;
                split2(av[t].z, av[t].w, h, l);
                sAh[arow[t]][aseg[t] * 2 + 1] = h; sAl[arow[t]][aseg[t] * 2 + 1] = l;
            }
#pragma unroll
            for (int p = 0; p < 4; p++) {
                split2(v2[2 * p], v2[2 * p + 1], h, l);
                sBh[bn][bkg * 4 + p] = h; sBl[bn][bkg * 4 + p] = l;
            }
        }
        __syncthreads();
        if (c + 1 < NCH2) load_regs(c + 1);
#pragma unroll
        for (int ks = 0; ks < 2; ks++) {
            uint32_t ah[2][4], al[2][4];
#pragma unroll
            for (int mt = 0; mt < 2; mt++) {
                ldm_x4(ah[mt], ldm_addr(bAh, lane, m0 + mt * 16, ks));
                ldm_x4(al[mt], ldm_addr(bAl, lane, m0 + mt * 16, ks));
            }
#pragma unroll
            for (int g = 0; g < 2; g++) {
                uint32_t fh[4], fl[4];
                ldm_x4(fh, ldm_addr(bBh, lane, n0 + g * 16, ks));
                ldm_x4(fl, ldm_addr(bBl, lane, n0 + g * 16, ks));
#pragma unroll
                for (int h2 = 0; h2 < 2; h2++) {
                    int nt = g * 2 + h2;
                    uint32_t bhF[2] = { fh[h2], fh[h2 + 2] };
                    uint32_t blF[2] = { fl[h2], fl[h2 + 2] };
#pragma unroll
                    for (int mt = 0; mt < 2; mt++) {
                        mma16816(acc[mt][nt], ah[mt], bhF);
                        mma16816(acc[mt][nt], ah[mt], blF);
                        mma16816(acc[mt][nt], al[mt], bhF);
                    }
                }
            }
        }
    }

    // epilogue
#pragma unroll
    for (int mt = 0; mt < 2; mt++)
#pragma unroll
        for (int hf = 0; hf < 2; hf++) {
            int r = rowBase + m0 + mt * 16 + grp + hf * 8;
            if (r < n) {
                int slot = g_entry[e * T_TOK + r];
                float wgt = g_topw[slot];
                size_t to = (size_t)(slot >> 1) * DIM;
#pragma unroll
                for (int nt = 0; nt < 4; nt++) {
                    int col = colBase + n0 + nt * 8 + t4 * 2;
                    float2 o = *(float2*)(out + to + col);
                    o.x += wgt * acc[mt][nt][hf * 2 + 0];
                    o.y += wgt * acc[mt][nt][hf * 2 + 1];
                    *(float2*)(out + to + col) = o;
                }
            }
        }
}

// ------------------------- launch -------------------------
extern "C" void kernel_launch(void* const* d_in, const int* in_sizes, int n_in,
                              void* d_out, int out_size) {
    const float* x  = (const float*)d_in[0];
    const float* gw = (const float*)d_in[1];
    const float* w1 = (const float*)d_in[2];
    const float* w2 = (const float*)d_in[3];
    const float* w3 = (const float*)d_in[4];
    float* out = (float*)d_out;

    const int out_elems = T_TOK * DIM;
    const int out_elems4 = out_elems / 4;

    init_kernel<<<(out_elems4 + 255) / 256, 256>>>(out, out_elems4);
    router_kernel<<<T_TOK / 8, 256>>>(x, gw);
    aux_kernel<<<1, 1>>>(out, (out_size > out_elems) ? 1 : 0);

    for (int e = 0; e < NE; e++) {
        gemm13_mma_kernel<<<dim3(T_TOK / 128, HID / 64), 256>>>(x, w1, w3, e);
        gemm2_mma_kernel<<<dim3(T_TOK / 128, DIM / 64), 256>>>(w2, out, e);
    }
}

// round 9
// speedup vs baseline: 2.4145x; 1.0234x over previous
#include <cuda_runtime.h>
#include <cuda_bf16.h>
#include <cstdint>
#include <math.h>

#define T_TOK 8192
#define DIM   1024
#define HID   4096
#define NE    8
#define KCH   16
#define PAD   12   // u32 row stride = 48B: 16B-aligned for ldmatrix, conflict-free (12i mod 32 distinct)

// ------------------------- scratch -------------------------
__device__ float g_H2[(size_t)2 * T_TOK * HID];   // hidden acts indexed by dispatch slot (tok*2+k)
__device__ int   g_entry[NE * T_TOK];
__device__ float g_topw[2 * T_TOK];
__device__ int   g_cnt[NE];
__device__ float g_usage[NE];

// ------------------------- helpers -------------------------
__device__ __forceinline__ uint32_t smem_to_u32(const void* p) {
    uint32_t a;
    asm("{ .reg .u64 t; cvta.to.shared.u64 t, %1; cvt.u32.u64 %0, t; }" : "=r"(a) : "l"(p));
    return a;
}
__device__ __forceinline__ void ldm_x4(uint32_t* f, uint32_t addr) {
    asm volatile("ldmatrix.sync.aligned.m8n8.x4.shared.b16 {%0,%1,%2,%3}, [%4];"
        : "=r"(f[0]), "=r"(f[1]), "=r"(f[2]), "=r"(f[3]) : "r"(addr));
}
// lane address into padded [rows][PAD] u32 tile, one k16 step (cols 0..7)
__device__ __forceinline__ uint32_t ldm_addr(uint32_t base, int lane, int row0) {
    int r = row0 + (lane & 7) + ((lane >> 3) & 1) * 8;
    int c = (lane >> 4) * 4;
    return base + (uint32_t)(r * PAD + c) * 4u;
}
__device__ __forceinline__ void mma16816(float* c, const uint32_t* a, const uint32_t* b) {
    asm volatile(
        "mma.sync.aligned.m16n8k16.row.col.f32.bf16.bf16.f32 "
        "{%0,%1,%2,%3}, {%4,%5,%6,%7}, {%8,%9}, {%0,%1,%2,%3};"
        : "+f"(c[0]), "+f"(c[1]), "+f"(c[2]), "+f"(c[3])
        : "r"(a[0]), "r"(a[1]), "r"(a[2]), "r"(a[3]), "r"(b[0]), "r"(b[1]));
}
__device__ __forceinline__ uint32_t pack_bf2(__nv_bfloat16 a, __nv_bfloat16 b) {
    return (uint32_t)__bfloat16_as_ushort(a) | ((uint32_t)__bfloat16_as_ushort(b) << 16);
}
__device__ __forceinline__ void split2(float f0, float f1, uint32_t& hi, uint32_t& lo) {
    __nv_bfloat16 h0 = __float2bfloat16(f0);
    __nv_bfloat16 h1 = __float2bfloat16(f1);
    __nv_bfloat16 l0 = __float2bfloat16(f0 - __bfloat162float(h0));
    __nv_bfloat16 l1 = __float2bfloat16(f1 - __bfloat162float(h1));
    hi = pack_bf2(h0, h1);
    lo = pack_bf2(l0, l1);
}

// ------------------------- init / router / aux -------------------------
__global__ void init_kernel(float* out, int out_elems4) {
    int i = blockIdx.x * blockDim.x + threadIdx.x;
    if (i < out_elems4) ((float4*)out)[i] = make_float4(0.f, 0.f, 0.f, 0.f);
    if (i < NE) { g_cnt[i] = 0; g_usage[i] = 0.f; }
}

__global__ void router_kernel(const float* __restrict__ x, const float* __restrict__ gw) {
    int warp = (blockIdx.x * blockDim.x + threadIdx.x) >> 5;
    int lane = threadIdx.x & 31;
    if (warp >= T_TOK) return;
    const float* xr = x + (size_t)warp * DIM;
    float acc[NE];
#pragma unroll
    for (int e = 0; e < NE; e++) acc[e] = 0.f;
    for (int d = lane; d < DIM; d += 32) {
        float xv = xr[d];
#pragma unroll
        for (int e = 0; e < NE; e++) acc[e] = fmaf(xv, gw[d * NE + e], acc[e]);
    }
#pragma unroll
    for (int off = 16; off; off >>= 1)
#pragma unroll
        for (int e = 0; e < NE; e++) acc[e] += __shfl_xor_sync(0xffffffffu, acc[e], off);
    if (lane == 0) {
        float m = acc[0];
#pragma unroll
        for (int e = 1; e < NE; e++) m = fmaxf(m, acc[e]);
        float Z = 0.f, p[NE];
#pragma unroll
        for (int e = 0; e < NE; e++) { p[e] = expf(acc[e] - m); Z += p[e]; }
        float invZ = 1.f / Z;
#pragma unroll
        for (int e = 0; e < NE; e++) atomicAdd(&g_usage[e], p[e] * invZ);
        int i0 = 0;
#pragma unroll
        for (int e = 1; e < NE; e++) if (acc[e] > acc[i0]) i0 = e;
        int i1 = (i0 == 0) ? 1 : 0;
#pragma unroll
        for (int e = 0; e < NE; e++) if (e != i0 && acc[e] > acc[i1]) i1 = e;
        float e1 = expf(acc[i1] - acc[i0]);
        float w0 = 1.f / (1.f + e1);
        g_topw[2 * warp]     = w0;
        g_topw[2 * warp + 1] = e1 * w0;
        int p0 = atomicAdd(&g_cnt[i0], 1);
        g_entry[i0 * T_TOK + p0] = warp * 2;
        int p1 = atomicAdd(&g_cnt[i1], 1);
        g_entry[i1 * T_TOK + p1] = warp * 2 + 1;
    }
}

__global__ void aux_kernel(float* out, int has_aux) {
    if (!has_aux) return;
    float s = 0.f;
#pragma unroll
    for (int e = 0; e < NE; e++) { float u = g_usage[e] / (float)T_TOK; s += u * u; }
    out[(size_t)T_TOK * DIM] = (float)NE * s;
}

// ------------------------- GEMM 1&3 fused over experts -------------------------
// grid (T_TOK/128, HID/64, NE); CTA 128x64; warp m32 x n32 (c1 AND c3).
// Double-buffered KCH=16 stages; 1 sync per chunk. Smem = exactly 48KB.
#define NCH13 (DIM / KCH)

__global__ __launch_bounds__(256)
void gemm13_mma_kernel(const float* __restrict__ x, const float* __restrict__ w1,
                       const float* __restrict__ w3)
{
    __shared__ uint32_t sAh[2][128][PAD], sAl[2][128][PAD];
    __shared__ uint32_t sB1h[2][64][PAD], sB1l[2][64][PAD];
    __shared__ uint32_t sB3h[2][64][PAD], sB3l[2][64][PAD];

    int e = blockIdx.z;
    int n = g_cnt[e];
    int rowBase = blockIdx.x * 128;
    if (rowBase >= n) return;
    int colBase = blockIdx.y * 64;
    int tid = threadIdx.x, wid = tid >> 5, lane = tid & 31;
    int m0 = (wid & 3) * 32, n0 = (wid >> 2) * 32;
    int grp = lane >> 2, t4 = lane & 3;

    // A: 2 float4 per thread; rows 0..127, 4 segs of 4 floats
    int arow[2], aseg[2];
#pragma unroll
    for (int t = 0; t < 2; t++) { int idx = tid + t * 256; arow[t] = idx >> 2; aseg[t] = idx & 3; }
    // B: 4 strided floats per matrix; n = tid&63, k-group tid>>6 (4 k each)
    int bn = tid & 63, bkg = tid >> 6;

    const size_t ebW = (size_t)e * DIM * HID;
    const float* pA[2];
#pragma unroll
    for (int t = 0; t < 2; t++) {
        int r = rowBase + arow[t];
        int slot = (r < n) ? g_entry[e * T_TOK + r] : 0;
        pA[t] = x + (size_t)(slot >> 1) * DIM + aseg[t] * 4;
    }
    const float* p1 = w1 + ebW + (size_t)(bkg * 4) * HID + colBase + bn;
    const float* p3 = w3 + ebW + (size_t)(bkg * 4) * HID + colBase + bn;

    float4 av[2];
    float v1[4], v3[4];

    auto load_regs = [&]() {
#pragma unroll
        for (int t = 0; t < 2; t++) { av[t] = *(const float4*)pA[t]; pA[t] += KCH; }
#pragma unroll
        for (int j = 0; j < 4; j++) { v1[j] = p1[(size_t)j * HID]; v3[j] = p3[(size_t)j * HID]; }
        p1 += (size_t)KCH * HID; p3 += (size_t)KCH * HID;
    };
    auto sts = [&](int st) {
        uint32_t h, l;
#pragma unroll
        for (int t = 0; t < 2; t++) {
            split2(av[t].x, av[t].y, h, l);
            sAh[st][arow[t]][aseg[t] * 2] = h;     sAl[st][arow[t]][aseg[t] * 2] = l;
            split2(av[t].z, av[t].w, h, l);
            sAh[st][arow[t]][aseg[t] * 2 + 1] = h; sAl[st][arow[t]][aseg[t] * 2 + 1] = l;
        }
        split2(v1[0], v1[1], h, l); sB1h[st][bn][bkg * 2] = h;     sB1l[st][bn][bkg * 2] = l;
        split2(v1[2], v1[3], h, l); sB1h[st][bn][bkg * 2 + 1] = h; sB1l[st][bn][bkg * 2 + 1] = l;
        split2(v3[0], v3[1], h, l); sB3h[st][bn][bkg * 2] = h;     sB3l[st][bn][bkg * 2] = l;
        split2(v3[2], v3[3], h, l); sB3h[st][bn][bkg * 2 + 1] = h; sB3l[st][bn][bkg * 2 + 1] = l;
    };

    float c1[2][4][4], c3[2][4][4];
#pragma unroll
    for (int mt = 0; mt < 2; mt++)
#pragma unroll
        for (int j = 0; j < 4; j++)
#pragma unroll
            for (int q = 0; q < 4; q++) { c1[mt][j][q] = 0.f; c3[mt][j][q] = 0.f; }

    load_regs(); sts(0); load_regs();

    for (int c = 0; c < NCH13; c++) {
        int st = c & 1;
        __syncthreads();                       // stage st fully written; other stage free
        if (c + 1 < NCH13) sts(st ^ 1);        // overlaps with MMA below (across warps)
        if (c + 2 < NCH13) load_regs();
        uint32_t ah[2][4], al[2][4];
#pragma unroll
        for (int mt = 0; mt < 2; mt++) {
            ldm_x4(ah[mt], ldm_addr(smem_to_u32(sAh[st]), lane, m0 + mt * 16));
            ldm_x4(al[mt], ldm_addr(smem_to_u32(sAl[st]), lane, m0 + mt * 16));
        }
#pragma unroll
        for (int g = 0; g < 2; g++) {
            uint32_t f1h[4], f1l[4], f3h[4], f3l[4];
            ldm_x4(f1h, ldm_addr(smem_to_u32(sB1h[st]), lane, n0 + g * 16));
            ldm_x4(f1l, ldm_addr(smem_to_u32(sB1l[st]), lane, n0 + g * 16));
            ldm_x4(f3h, ldm_addr(smem_to_u32(sB3h[st]), lane, n0 + g * 16));
            ldm_x4(f3l, ldm_addr(smem_to_u32(sB3l[st]), lane, n0 + g * 16));
#pragma unroll
            for (int h2 = 0; h2 < 2; h2++) {
                int nt = g * 2 + h2;
                uint32_t b1hF[2] = { f1h[h2], f1h[h2 + 2] };
                uint32_t b1lF[2] = { f1l[h2], f1l[h2 + 2] };
                uint32_t b3hF[2] = { f3h[h2], f3h[h2 + 2] };
                uint32_t b3lF[2] = { f3l[h2], f3l[h2 + 2] };
#pragma unroll
                for (int mt = 0; mt < 2; mt++) {
                    mma16816(c1[mt][nt], ah[mt], b1hF);
                    mma16816(c1[mt][nt], ah[mt], b1lF);
                    mma16816(c1[mt][nt], al[mt], b1hF);
                    mma16816(c3[mt][nt], ah[mt], b3hF);
                    mma16816(c3[mt][nt], ah[mt], b3lF);
                    mma16816(c3[mt][nt], al[mt], b3hF);
                }
            }
        }
    }

    // epilogue: h = silu(c1) * c3 -> g_H2[slot]
#pragma unroll
    for (int mt = 0; mt < 2; mt++)
#pragma unroll
        for (int hf = 0; hf < 2; hf++) {
            int rr = m0 + mt * 16 + grp + hf * 8;
            int r = rowBase + rr;
            if (r < n) {
                int slot = g_entry[e * T_TOK + r];
#pragma unroll
                for (int nt = 0; nt < 4; nt++) {
                    int col = colBase + n0 + nt * 8 + t4 * 2;
                    float a0 = c1[mt][nt][hf * 2 + 0], b0 = c3[mt][nt][hf * 2 + 0];
                    float a1 = c1[mt][nt][hf * 2 + 1], b1 = c3[mt][nt][hf * 2 + 1];
                    float h0 = (a0 / (1.f + expf(-a0))) * b0;
                    float h1 = (a1 / (1.f + expf(-a1))) * b1;
                    *(float2*)(g_H2 + (size_t)slot * HID + col) = make_float2(h0, h1);
                }
            }
        }
}

// ------------------------- GEMM 2 fused over experts -------------------------
// grid (T_TOK/128, DIM/64, NE); CTA 128x64; warp m32 x n32. atomicAdd into out.
#define NCH2 (HID / KCH)

__global__ __launch_bounds__(256)
void gemm2_mma_kernel(const float* __restrict__ w2, float* __restrict__ out)
{
    __shared__ uint32_t sAh[2][128][PAD], sAl[2][128][PAD];
    __shared__ uint32_t sBh[2][64][PAD], sBl[2][64][PAD];
    __shared__ int sSlot[128];

    int e = blockIdx.z;
    int n = g_cnt[e];
    int rowBase = blockIdx.x * 128;
    if (rowBase >= n) return;
    int colBase = blockIdx.y * 64;
    int tid = threadIdx.x, wid = tid >> 5, lane = tid & 31;
    int m0 = (wid & 3) * 32, n0 = (wid >> 2) * 32;
    int grp = lane >> 2, t4 = lane & 3;

    if (tid < 128) {
        int r = rowBase + tid;
        sSlot[tid] = (r < n) ? g_entry[e * T_TOK + r] : 0;
    }
    __syncthreads();

    int arow[2], aseg[2];
#pragma unroll
    for (int t = 0; t < 2; t++) { int idx = tid + t * 256; arow[t] = idx >> 2; aseg[t] = idx & 3; }
    int bn = tid & 63, bkg = tid >> 6;

    const size_t ebW = (size_t)e * HID * DIM;
    const float* pA[2];
#pragma unroll
    for (int t = 0; t < 2; t++)
        pA[t] = g_H2 + (size_t)sSlot[arow[t]] * HID + aseg[t] * 4;
    const float* p2 = w2 + ebW + (size_t)(bkg * 4) * DIM + colBase + bn;

    float4 av[2];
    float v2[4];

    auto load_regs = [&]() {
#pragma unroll
        for (int t = 0; t < 2; t++) { av[t] = *(const float4*)pA[t]; pA[t] += KCH; }
#pragma unroll
        for (int j = 0; j < 4; j++) v2[j] = p2[(size_t)j * DIM];
        p2 += (size_t)KCH * DIM;
    };
    auto sts = [&](int st) {
        uint32_t h, l;
#pragma unroll
        for (int t = 0; t < 2; t++) {
            split2(av[t].x, av[t].y, h, l);
            sAh[st][arow[t]][aseg[t] * 2] = h;     sAl[st][arow[t]][aseg[t] * 2] = l;
            split2(av[t].z, av[t].w, h, l);
            sAh[st][arow[t]][aseg[t] * 2 + 1] = h; sAl[st][arow[t]][aseg[t] * 2 + 1] = l;
        }
        split2(v2[0], v2[1], h, l); sBh[st][bn][bkg * 2] = h;     sBl[st][bn][bkg * 2] = l;
        split2(v2[2], v2[3], h, l); sBh[st][bn][bkg * 2 + 1] = h; sBl[st][bn][bkg * 2 + 1] = l;
    };

    float acc[2][4][4];
#pragma unroll
    for (int mt = 0; mt < 2; mt++)
#pragma unroll
        for (int j = 0; j < 4; j++)
#pragma unroll
            for (int q = 0; q < 4; q++) acc[mt][j][q] = 0.f;

    load_regs(); sts(0); load_regs();

    for (int c = 0; c < NCH2; c++) {
        int st = c & 1;
        __syncthreads();
        if (c + 1 < NCH2) sts(st ^ 1);
        if (c + 2 < NCH2) load_regs();
        uint32_t ah[2][4], al[2][4];
#pragma unroll
        for (int mt = 0; mt < 2; mt++) {
            ldm_x4(ah[mt], ldm_addr(smem_to_u32(sAh[st]), lane, m0 + mt * 16));
            ldm_x4(al[mt], ldm_addr(smem_to_u32(sAl[st]), lane, m0 + mt * 16));
        }
#pragma unroll
        for (int g = 0; g < 2; g++) {
            uint32_t fh[4], fl[4];
            ldm_x4(fh, ldm_addr(smem_to_u32(sBh[st]), lane, n0 + g * 16));
            ldm_x4(fl, ldm_addr(smem_to_u32(sBl[st]), lane, n0 + g * 16));
#pragma unroll
            for (int h2 = 0; h2 < 2; h2++) {
                int nt = g * 2 + h2;
                uint32_t bhF[2] = { fh[h2], fh[h2 + 2] };
                uint32_t blF[2] = { fl[h2], fl[h2 + 2] };
#pragma unroll
                for (int mt = 0; mt < 2; mt++) {
                    mma16816(acc[mt][nt], ah[mt], bhF);
                    mma16816(acc[mt][nt], ah[mt], blF);
                    mma16816(acc[mt][nt], al[mt], bhF);
                }
            }
        }
    }

    // epilogue: atomic combine into out
#pragma unroll
    for (int mt = 0; mt < 2; mt++)
#pragma unroll
        for (int hf = 0; hf < 2; hf++) {
            int rr = m0 + mt * 16 + grp + hf * 8;
            int r = rowBase + rr;
            if (r < n) {
                int slot = sSlot[rr];
                float wgt = g_topw[slot];
                float* op = out + (size_t)(slot >> 1) * DIM;
#pragma unroll
                for (int nt = 0; nt < 4; nt++) {
                    int col = colBase + n0 + nt * 8 + t4 * 2;
                    atomicAdd(op + col,     wgt * acc[mt][nt][hf * 2 + 0]);
                    atomicAdd(op + col + 1, wgt * acc[mt][nt][hf * 2 + 1]);
                }
            }
        }
}

// ------------------------- launch -------------------------
extern "C" void kernel_launch(void* const* d_in, const int* in_sizes, int n_in,
                              void* d_out, int out_size) {
    const float* x  = (const float*)d_in[0];
    const float* gw = (const float*)d_in[1];
    const float* w1 = (const float*)d_in[2];
    const float* w2 = (const float*)d_in[3];
    const float* w3 = (const float*)d_in[4];
    float* out = (float*)d_out;

    const int out_elems = T_TOK * DIM;
    const int out_elems4 = out_elems / 4;

    init_kernel<<<(out_elems4 + 255) / 256, 256>>>(out, out_elems4);
    router_kernel<<<T_TOK / 8, 256>>>(x, gw);
    aux_kernel<<<1, 1>>>(out, (out_size > out_elems) ? 1 : 0);

    gemm13_mma_kernel<<<dim3(T_TOK / 128, HID / 64, NE), 256>>>(x, w1, w3);
    gemm2_mma_kernel<<<dim3(T_TOK / 128, DIM / 64, NE), 256>>>(w2, out);
}

// round 10
// speedup vs baseline: 2.5409x; 1.0524x over previous
#include <cuda_runtime.h>
#include <cuda_bf16.h>
#include <cstdint>
#include <math.h>

#define T_TOK 8192
#define DIM   1024
#define HID   4096
#define NE    8
#define KCH   16
#define PAD   12   // u32 row stride = 48B: 16B-aligned for ldmatrix, conflict-free

// ------------------------- scratch -------------------------
__device__ float g_H2[(size_t)2 * T_TOK * HID];   // hidden acts indexed by dispatch slot (tok*2+k)
__device__ int   g_entry[NE * T_TOK];
__device__ float g_topw[2 * T_TOK];
__device__ int   g_cnt[NE];
__device__ float g_usage[NE];

// ------------------------- helpers -------------------------
__device__ __forceinline__ uint32_t smem_to_u32(const void* p) {
    uint32_t a;
    asm("{ .reg .u64 t; cvta.to.shared.u64 t, %1; cvt.u32.u64 %0, t; }" : "=r"(a) : "l"(p));
    return a;
}
__device__ __forceinline__ void ldm_x4(uint32_t* f, uint32_t addr) {
    asm volatile("ldmatrix.sync.aligned.m8n8.x4.shared.b16 {%0,%1,%2,%3}, [%4];"
        : "=r"(f[0]), "=r"(f[1]), "=r"(f[2]), "=r"(f[3]) : "r"(addr));
}
__device__ __forceinline__ void mma16816(float* c, const uint32_t* a, const uint32_t* b) {
    asm volatile(
        "mma.sync.aligned.m16n8k16.row.col.f32.bf16.bf16.f32 "
        "{%0,%1,%2,%3}, {%4,%5,%6,%7}, {%8,%9}, {%0,%1,%2,%3};"
        : "+f"(c[0]), "+f"(c[1]), "+f"(c[2]), "+f"(c[3])
        : "r"(a[0]), "r"(a[1]), "r"(a[2]), "r"(a[3]), "r"(b[0]), "r"(b[1]));
}
__device__ __forceinline__ uint32_t pack_bf2(__nv_bfloat16 a, __nv_bfloat16 b) {
    return (uint32_t)__bfloat16_as_ushort(a) | ((uint32_t)__bfloat16_as_ushort(b) << 16);
}
__device__ __forceinline__ void split2(float f0, float f1, uint32_t& hi, uint32_t& lo) {
    __nv_bfloat16 h0 = __float2bfloat16(f0);
    __nv_bfloat16 h1 = __float2bfloat16(f1);
    __nv_bfloat16 l0 = __float2bfloat16(f0 - __bfloat162float(h0));
    __nv_bfloat16 l1 = __float2bfloat16(f1 - __bfloat162float(h1));
    hi = pack_bf2(h0, h1);
    lo = pack_bf2(l0, l1);
}
// lane-dependent ldmatrix offset within a padded tile (row0 added by caller)
__device__ __forceinline__ uint32_t lane_off(int lane) {
    return (uint32_t)(((lane & 7) + ((lane >> 3) & 1) * 8) * (PAD * 4) + (lane >> 4) * 16);
}

// ------------------------- init / router / aux -------------------------
__global__ void init_kernel(float* out, int out_elems4) {
    int i = blockIdx.x * blockDim.x + threadIdx.x;
    if (i < out_elems4) ((float4*)out)[i] = make_float4(0.f, 0.f, 0.f, 0.f);
    if (i < NE) { g_cnt[i] = 0; g_usage[i] = 0.f; }
}

__global__ void router_kernel(const float* __restrict__ x, const float* __restrict__ gw) {
    int warp = (blockIdx.x * blockDim.x + threadIdx.x) >> 5;
    int lane = threadIdx.x & 31;
    if (warp >= T_TOK) return;
    const float* xr = x + (size_t)warp * DIM;
    float acc[NE];
#pragma unroll
    for (int e = 0; e < NE; e++) acc[e] = 0.f;
    for (int d = lane; d < DIM; d += 32) {
        float xv = xr[d];
#pragma unroll
        for (int e = 0; e < NE; e++) acc[e] = fmaf(xv, gw[d * NE + e], acc[e]);
    }
#pragma unroll
    for (int off = 16; off; off >>= 1)
#pragma unroll
        for (int e = 0; e < NE; e++) acc[e] += __shfl_xor_sync(0xffffffffu, acc[e], off);
    if (lane == 0) {
        float m = acc[0];
#pragma unroll
        for (int e = 1; e < NE; e++) m = fmaxf(m, acc[e]);
        float Z = 0.f, p[NE];
#pragma unroll
        for (int e = 0; e < NE; e++) { p[e] = expf(acc[e] - m); Z += p[e]; }
        float invZ = 1.f / Z;
#pragma unroll
        for (int e = 0; e < NE; e++) atomicAdd(&g_usage[e], p[e] * invZ);
        int i0 = 0;
#pragma unroll
        for (int e = 1; e < NE; e++) if (acc[e] > acc[i0]) i0 = e;
        int i1 = (i0 == 0) ? 1 : 0;
#pragma unroll
        for (int e = 0; e < NE; e++) if (e != i0 && acc[e] > acc[i1]) i1 = e;
        float e1 = expf(acc[i1] - acc[i0]);
        float w0 = 1.f / (1.f + e1);
        g_topw[2 * warp]     = w0;
        g_topw[2 * warp + 1] = e1 * w0;
        int p0 = atomicAdd(&g_cnt[i0], 1);
        g_entry[i0 * T_TOK + p0] = warp * 2;
        int p1 = atomicAdd(&g_cnt[i1], 1);
        g_entry[i1 * T_TOK + p1] = warp * 2 + 1;
    }
}

__global__ void aux_kernel(float* out, int has_aux) {
    if (!has_aux) return;
    float s = 0.f;
#pragma unroll
    for (int e = 0; e < NE; e++) { float u = g_usage[e] / (float)T_TOK; s += u * u; }
    out[(size_t)T_TOK * DIM] = (float)NE * s;
}

// ------------------------- GEMM 1&3 fused over experts -------------------------
#define NCH13 (DIM / KCH)

__global__ __launch_bounds__(256, 2)
void gemm13_mma_kernel(const float* __restrict__ x, const float* __restrict__ w1,
                       const float* __restrict__ w3)
{
    __shared__ uint32_t sAh[2][128][PAD], sAl[2][128][PAD];
    __shared__ uint32_t sB1h[2][64][PAD], sB1l[2][64][PAD];
    __shared__ uint32_t sB3h[2][64][PAD], sB3l[2][64][PAD];

    int e = blockIdx.z;
    int n = g_cnt[e];
    int rowBase = blockIdx.x * 128;
    if (rowBase >= n) return;
    int colBase = blockIdx.y * 64;
    int tid = threadIdx.x, wid = tid >> 5, lane = tid & 31;
    int m0 = (wid & 3) * 32, n0 = (wid >> 2) * 32;
    int grp = lane >> 2, t4 = lane & 3;

    int arow[2], aseg[2];
#pragma unroll
    for (int t = 0; t < 2; t++) { int idx = tid + t * 256; arow[t] = idx >> 2; aseg[t] = idx & 3; }
    int bn = tid & 63, bkg = tid >> 6;

    const size_t ebW = (size_t)e * DIM * HID;
    const float* pA[2];
#pragma unroll
    for (int t = 0; t < 2; t++) {
        int r = rowBase + arow[t];
        int slot = (r < n) ? g_entry[e * T_TOK + r] : 0;
        pA[t] = x + (size_t)(slot >> 1) * DIM + aseg[t] * 4;
    }
    const float* p1 = w1 + ebW + (size_t)(bkg * 4) * HID + colBase + bn;
    const float* p3 = w3 + ebW + (size_t)(bkg * 4) * HID + colBase + bn;

    // hoisted ldmatrix bases (per stage, per tile): base + laneoff + warp row0
    uint32_t lo = lane_off(lane);
    uint32_t bAH[2], bAL[2], b1H[2], b1L[2], b3H[2], b3L[2];
#pragma unroll
    for (int st = 0; st < 2; st++) {
        bAH[st] = smem_to_u32(sAh[st]) + lo + (uint32_t)m0 * (PAD * 4);
        bAL[st] = smem_to_u32(sAl[st]) + lo + (uint32_t)m0 * (PAD * 4);
        b1H[st] = smem_to_u32(sB1h[st]) + lo + (uint32_t)n0 * (PAD * 4);
        b1L[st] = smem_to_u32(sB1l[st]) + lo + (uint32_t)n0 * (PAD * 4);
        b3H[st] = smem_to_u32(sB3h[st]) + lo + (uint32_t)n0 * (PAD * 4);
        b3L[st] = smem_to_u32(sB3l[st]) + lo + (uint32_t)n0 * (PAD * 4);
    }

    float4 av[2];
    float v1[4], v3[4];

    auto load_regs = [&]() {
#pragma unroll
        for (int t = 0; t < 2; t++) { av[t] = *(const float4*)pA[t]; pA[t] += KCH; }
#pragma unroll
        for (int j = 0; j < 4; j++) { v1[j] = p1[(size_t)j * HID]; v3[j] = p3[(size_t)j * HID]; }
        p1 += (size_t)KCH * HID; p3 += (size_t)KCH * HID;
    };
    auto sts = [&](int st) {
        uint32_t h, l;
#pragma unroll
        for (int t = 0; t < 2; t++) {
            split2(av[t].x, av[t].y, h, l);
            sAh[st][arow[t]][aseg[t] * 2] = h;     sAl[st][arow[t]][aseg[t] * 2] = l;
            split2(av[t].z, av[t].w, h, l);
            sAh[st][arow[t]][aseg[t] * 2 + 1] = h; sAl[st][arow[t]][aseg[t] * 2 + 1] = l;
        }
        split2(v1[0], v1[1], h, l); sB1h[st][bn][bkg * 2] = h;     sB1l[st][bn][bkg * 2] = l;
        split2(v1[2], v1[3], h, l); sB1h[st][bn][bkg * 2 + 1] = h; sB1l[st][bn][bkg * 2 + 1] = l;
        split2(v3[0], v3[1], h, l); sB3h[st][bn][bkg * 2] = h;     sB3l[st][bn][bkg * 2] = l;
        split2(v3[2], v3[3], h, l); sB3h[st][bn][bkg * 2 + 1] = h; sB3l[st][bn][bkg * 2 + 1] = l;
    };

    float c1[2][4][4], c3[2][4][4];
#pragma unroll
    for (int mt = 0; mt < 2; mt++)
#pragma unroll
        for (int j = 0; j < 4; j++)
#pragma unroll
            for (int q = 0; q < 4; q++) { c1[mt][j][q] = 0.f; c3[mt][j][q] = 0.f; }

    load_regs(); sts(0); load_regs();

    for (int c = 0; c < NCH13; c++) {
        int st = c & 1;
        __syncthreads();
        if (c + 1 < NCH13) sts(st ^ 1);
        if (c + 2 < NCH13) load_regs();
        uint32_t ah[2][4], al[2][4];
#pragma unroll
        for (int mt = 0; mt < 2; mt++) {
            ldm_x4(ah[mt], bAH[st] + mt * 16 * (PAD * 4));
            ldm_x4(al[mt], bAL[st] + mt * 16 * (PAD * 4));
        }
#pragma unroll
        for (int g = 0; g < 2; g++) {
            uint32_t f1h[4], f1l[4], f3h[4], f3l[4];
            ldm_x4(f1h, b1H[st] + g * 16 * (PAD * 4));
            ldm_x4(f1l, b1L[st] + g * 16 * (PAD * 4));
            ldm_x4(f3h, b3H[st] + g * 16 * (PAD * 4));
            ldm_x4(f3l, b3L[st] + g * 16 * (PAD * 4));
#pragma unroll
            for (int h2 = 0; h2 < 2; h2++) {
                int nt = g * 2 + h2;
                uint32_t b1hF[2] = { f1h[h2], f1h[h2 + 2] };
                uint32_t b1lF[2] = { f1l[h2], f1l[h2 + 2] };
                uint32_t b3hF[2] = { f3h[h2], f3h[h2 + 2] };
                uint32_t b3lF[2] = { f3l[h2], f3l[h2 + 2] };
#pragma unroll
                for (int mt = 0; mt < 2; mt++) {
                    mma16816(c1[mt][nt], ah[mt], b1hF);
                    mma16816(c1[mt][nt], ah[mt], b1lF);
                    mma16816(c1[mt][nt], al[mt], b1hF);
                    mma16816(c3[mt][nt], ah[mt], b3hF);
                    mma16816(c3[mt][nt], ah[mt], b3lF);
                    mma16816(c3[mt][nt], al[mt], b3hF);
                }
            }
        }
    }

    // epilogue: h = silu(c1) * c3 -> g_H2[slot]
#pragma unroll
    for (int mt = 0; mt < 2; mt++)
#pragma unroll
        for (int hf = 0; hf < 2; hf++) {
            int rr = m0 + mt * 16 + grp + hf * 8;
            int r = rowBase + rr;
            if (r < n) {
                int slot = g_entry[e * T_TOK + r];
#pragma unroll
                for (int nt = 0; nt < 4; nt++) {
                    int col = colBase + n0 + nt * 8 + t4 * 2;
                    float a0 = c1[mt][nt][hf * 2 + 0], b0 = c3[mt][nt][hf * 2 + 0];
                    float a1 = c1[mt][nt][hf * 2 + 1], b1 = c3[mt][nt][hf * 2 + 1];
                    float h0 = (a0 / (1.f + expf(-a0))) * b0;
                    float h1 = (a1 / (1.f + expf(-a1))) * b1;
                    *(float2*)(g_H2 + (size_t)slot * HID + col) = make_float2(h0, h1);
                }
            }
        }
}

// ------------------------- GEMM 2 fused over experts -------------------------
#define NCH2 (HID / KCH)

__global__ __launch_bounds__(256, 2)
void gemm2_mma_kernel(const float* __restrict__ w2, float* __restrict__ out)
{
    __shared__ uint32_t sAh[2][128][PAD], sAl[2][128][PAD];
    __shared__ uint32_t sBh[2][64][PAD], sBl[2][64][PAD];
    __shared__ int sSlot[128];

    int e = blockIdx.z;
    int n = g_cnt[e];
    int rowBase = blockIdx.x * 128;
    if (rowBase >= n) return;
    int colBase = blockIdx.y * 64;
    int tid = threadIdx.x, wid = tid >> 5, lane = tid & 31;
    int m0 = (wid & 3) * 32, n0 = (wid >> 2) * 32;
    int grp = lane >> 2, t4 = lane & 3;

    if (tid < 128) {
        int r = rowBase + tid;
        sSlot[tid] = (r < n) ? g_entry[e * T_TOK + r] : 0;
    }
    __syncthreads();

    int arow[2], aseg[2];
#pragma unroll
    for (int t = 0; t < 2; t++) { int idx = tid + t * 256; arow[t] = idx >> 2; aseg[t] = idx & 3; }
    int bn = tid & 63, bkg = tid >> 6;

    const size_t ebW = (size_t)e * HID * DIM;
    const float* pA[2];
#pragma unroll
    for (int t = 0; t < 2; t++)
        pA[t] = g_H2 + (size_t)sSlot[arow[t]] * HID + aseg[t] * 4;
    const float* p2 = w2 + ebW + (size_t)(bkg * 4) * DIM + colBase + bn;

    uint32_t lo = lane_off(lane);
    uint32_t bAH[2], bAL[2], bBH[2], bBL[2];
#pragma unroll
    for (int st = 0; st < 2; st++) {
        bAH[st] = smem_to_u32(sAh[st]) + lo + (uint32_t)m0 * (PAD * 4);
        bAL[st] = smem_to_u32(sAl[st]) + lo + (uint32_t)m0 * (PAD * 4);
        bBH[st] = smem_to_u32(sBh[st]) + lo + (uint32_t)n0 * (PAD * 4);
        bBL[st] = smem_to_u32(sBl[st]) + lo + (uint32_t)n0 * (PAD * 4);
    }

    float4 av[2];
    float v2[4];

    auto load_regs = [&]() {
#pragma unroll
        for (int t = 0; t < 2; t++) { av[t] = *(const float4*)pA[t]; pA[t] += KCH; }
#pragma unroll
        for (int j = 0; j < 4; j++) v2[j] = p2[(size_t)j * DIM];
        p2 += (size_t)KCH * DIM;
    };
    auto sts = [&](int st) {
        uint32_t h, l;
#pragma unroll
        for (int t = 0; t < 2; t++) {
            split2(av[t].x, av[t].y, h, l);
            sAh[st][arow[t]][aseg[t] * 2] = h;     sAl[st][arow[t]][aseg[t] * 2] = l;
            split2(av[t].z, av[t].w, h, l);
            sAh[st][arow[t]][aseg[t] * 2 + 1] = h; sAl[st][arow[t]][aseg[t] * 2 + 1] = l;
        }
        split2(v2[0], v2[1], h, l); sBh[st][bn][bkg * 2] = h;     sBl[st][bn][bkg * 2] = l;
        split2(v2[2], v2[3], h, l); sBh[st][bn][bkg * 2 + 1] = h; sBl[st][bn][bkg * 2 + 1] = l;
    };

    float acc[2][4][4];
#pragma unroll
    for (int mt = 0; mt < 2; mt++)
#pragma unroll
        for (int j = 0; j < 4; j++)
#pragma unroll
            for (int q = 0; q < 4; q++) acc[mt][j][q] = 0.f;

    load_regs(); sts(0); load_regs();

    for (int c = 0; c < NCH2; c++) {
        int st = c & 1;
        __syncthreads();
        if (c + 1 < NCH2) sts(st ^ 1);
        if (c + 2 < NCH2) load_regs();
        uint32_t ah[2][4], al[2][4];
#pragma unroll
        for (int mt = 0; mt < 2; mt++) {
            ldm_x4(ah[mt], bAH[st] + mt * 16 * (PAD * 4));
            ldm_x4(al[mt], bAL[st] + mt * 16 * (PAD * 4));
        }
#pragma unroll
        for (int g = 0; g < 2; g++) {
            uint32_t fh[4], fl[4];
            ldm_x4(fh, bBH[st] + g * 16 * (PAD * 4));
            ldm_x4(fl, bBL[st] + g * 16 * (PAD * 4));
#pragma unroll
            for (int h2 = 0; h2 < 2; h2++) {
                int nt = g * 2 + h2;
                uint32_t bhF[2] = { fh[h2], fh[h2 + 2] };
                uint32_t blF[2] = { fl[h2], fl[h2 + 2] };
#pragma unroll
                for (int mt = 0; mt < 2; mt++) {
                    mma16816(acc[mt][nt], ah[mt], bhF);
                    mma16816(acc[mt][nt], ah[mt], blF);
                    mma16816(acc[mt][nt], al[mt], bhF);
                }
            }
        }
    }

    // epilogue: atomic combine into out
#pragma unroll
    for (int mt = 0; mt < 2; mt++)
#pragma unroll
        for (int hf = 0; hf < 2; hf++) {
            int rr = m0 + mt * 16 + grp + hf * 8;
            int r = rowBase + rr;
            if (r < n) {
                int slot = sSlot[rr];
                float wgt = g_topw[slot];
                float* op = out + (size_t)(slot >> 1) * DIM;
#pragma unroll
                for (int nt = 0; nt < 4; nt++) {
                    int col = colBase + n0 + nt * 8 + t4 * 2;
                    atomicAdd(op + col,     wgt * acc[mt][nt][hf * 2 + 0]);
                    atomicAdd(op + col + 1, wgt * acc[mt][nt][hf * 2 + 1]);
                }
            }
        }
}

// ------------------------- launch -------------------------
extern "C" void kernel_launch(void* const* d_in, const int* in_sizes, int n_in,
                              void* d_out, int out_size) {
    const float* x  = (const float*)d_in[0];
    const float* gw = (const float*)d_in[1];
    const float* w1 = (const float*)d_in[2];
    const float* w2 = (const float*)d_in[3];
    const float* w3 = (const float*)d_in[4];
    float* out = (float*)d_out;

    const int out_elems = T_TOK * DIM;
    const int out_elems4 = out_elems / 4;

    init_kernel<<<(out_elems4 + 255) / 256, 256>>>(out, out_elems4);
    router_kernel<<<T_TOK / 8, 256>>>(x, gw);
    aux_kernel<<<1, 1>>>(out, (out_size > out_elems) ? 1 : 0);

    gemm13_mma_kernel<<<dim3(T_TOK / 128, HID / 64, NE), 256>>>(x, w1, w3);
    gemm2_mma_kernel<<<dim3(T_TOK / 128, DIM / 64, NE), 256>>>(w2, out);
}

// round 12
// speedup vs baseline: 3.6306x; 1.4288x over previous
#include <cuda_runtime.h>
#include <cuda_bf16.h>
#include <cstdint>
#include <math.h>

#define T_TOK 8192
#define DIM   1024
#define HID   4096
#define NE    8
#define KCH   16
#define PADA  12   // A tile u32 row stride (48B): proven conflict-free for ldmatrix
#define PADB  36   // B tile u32 row stride (144B): 16B-aligned, banks rotate by 4 -> conflict-free

// ------------------------- scratch: pre-split bf16 operands -------------------------
__device__ __nv_bfloat16 g_xh[(size_t)T_TOK * DIM],  g_xl[(size_t)T_TOK * DIM];
__device__ __nv_bfloat16 g_w1h[(size_t)NE * DIM * HID], g_w1l[(size_t)NE * DIM * HID]; // [E][k=D][n=H]
__device__ __nv_bfloat16 g_w3h[(size_t)NE * DIM * HID], g_w3l[(size_t)NE * DIM * HID]; // [E][k=D][n=H]
__device__ __nv_bfloat16 g_w2h[(size_t)NE * HID * DIM], g_w2l[(size_t)NE * HID * DIM]; // [E][k=H][n=D]
__device__ __nv_bfloat16 g_Hh[(size_t)2 * T_TOK * HID], g_Hl[(size_t)2 * T_TOK * HID]; // slot-major
__device__ int   g_entry[NE * T_TOK];
__device__ float g_topw[2 * T_TOK];
__device__ int   g_cnt[NE];
__device__ float g_usage[NE];

// ------------------------- helpers -------------------------
__device__ __forceinline__ uint32_t smem_to_u32(const void* p) {
    uint32_t a;
    asm("{ .reg .u64 t; cvta.to.shared.u64 t, %1; cvt.u32.u64 %0, t; }" : "=r"(a) : "l"(p));
    return a;
}
#define CP16(dst, src) asm volatile("cp.async.cg.shared.global [%0], [%1], 16;" :: "r"(dst), "l"(src))
#define CP_COMMIT() asm volatile("cp.async.commit_group;" ::: "memory")
#define CP_WAIT0()  asm volatile("cp.async.wait_group 0;" ::: "memory")

__device__ __forceinline__ void ldm_x4(uint32_t* f, uint32_t addr) {
    asm volatile("ldmatrix.sync.aligned.m8n8.x4.shared.b16 {%0,%1,%2,%3}, [%4];"
        : "=r"(f[0]), "=r"(f[1]), "=r"(f[2]), "=r"(f[3]) : "r"(addr));
}
__device__ __forceinline__ void ldm_x4_t(uint32_t* f, uint32_t addr) {
    asm volatile("ldmatrix.sync.aligned.m8n8.x4.trans.shared.b16 {%0,%1,%2,%3}, [%4];"
        : "=r"(f[0]), "=r"(f[1]), "=r"(f[2]), "=r"(f[3]) : "r"(addr));
}
__device__ __forceinline__ void mma16816(float* c, const uint32_t* a, const uint32_t* b) {
    asm volatile(
        "mma.sync.aligned.m16n8k16.row.col.f32.bf16.bf16.f32 "
        "{%0,%1,%2,%3}, {%4,%5,%6,%7}, {%8,%9}, {%0,%1,%2,%3};"
        : "+f"(c[0]), "+f"(c[1]), "+f"(c[2]), "+f"(c[3])
        : "r"(a[0]), "r"(a[1]), "r"(a[2]), "r"(a[3]), "r"(b[0]), "r"(b[1]));
}
__device__ __forceinline__ uint32_t pack_bf2(__nv_bfloat16 a, __nv_bfloat16 b) {
    return (uint32_t)__bfloat16_as_ushort(a) | ((uint32_t)__bfloat16_as_ushort(b) << 16);
}
__device__ __forceinline__ void split2(float f0, float f1, uint32_t& hi, uint32_t& lo) {
    __nv_bfloat16 h0 = __float2bfloat16(f0);
    __nv_bfloat16 h1 = __float2bfloat16(f1);
    __nv_bfloat16 l0 = __float2bfloat16(f0 - __bfloat162float(h0));
    __nv_bfloat16 l1 = __float2bfloat16(f1 - __bfloat162float(h1));
    hi = pack_bf2(h0, h1);
    lo = pack_bf2(l0, l1);
}
__device__ __forceinline__ uint32_t lane_offA(int lane) {
    return (uint32_t)((((lane & 7) + ((lane >> 3) & 1) * 8)) * (PADA * 4) + (lane >> 4) * 16);
}
__device__ __forceinline__ uint32_t lane_offB(int lane) {
    return (uint32_t)((((lane & 7) + ((lane >> 3) & 1) * 8)) * (PADB * 4) + (lane >> 4) * 16);
}

// ------------------------- init / router / aux -------------------------
__global__ void init_kernel(float* out, int out_elems4) {
    int i = blockIdx.x * blockDim.x + threadIdx.x;
    if (i < out_elems4) ((float4*)out)[i] = make_float4(0.f, 0.f, 0.f, 0.f);
    if (i < NE) { g_cnt[i] = 0; g_usage[i] = 0.f; }
}

__global__ void router_kernel(const float* __restrict__ x, const float* __restrict__ gw) {
    int warp = (blockIdx.x * blockDim.x + threadIdx.x) >> 5;
    int lane = threadIdx.x & 31;
    if (warp >= T_TOK) return;
    const float* xr = x + (size_t)warp * DIM;
    float acc[NE];
#pragma unroll
    for (int e = 0; e < NE; e++) acc[e] = 0.f;
    for (int d = lane; d < DIM; d += 32) {
        float xv = xr[d];
#pragma unroll
        for (int e = 0; e < NE; e++) acc[e] = fmaf(xv, gw[d * NE + e], acc[e]);
    }
#pragma unroll
    for (int off = 16; off; off >>= 1)
#pragma unroll
        for (int e = 0; e < NE; e++) acc[e] += __shfl_xor_sync(0xffffffffu, acc[e], off);
    if (lane == 0) {
        float m = acc[0];
#pragma unroll
        for (int e = 1; e < NE; e++) m = fmaxf(m, acc[e]);
        float Z = 0.f, p[NE];
#pragma unroll
        for (int e = 0; e < NE; e++) { p[e] = expf(acc[e] - m); Z += p[e]; }
        float invZ = 1.f / Z;
#pragma unroll
        for (int e = 0; e < NE; e++) atomicAdd(&g_usage[e], p[e] * invZ);
        int i0 = 0;
#pragma unroll
        for (int e = 1; e < NE; e++) if (acc[e] > acc[i0]) i0 = e;
        int i1 = (i0 == 0) ? 1 : 0;
#pragma unroll
        for (int e = 0; e < NE; e++) if (e != i0 && acc[e] > acc[i1]) i1 = e;
        float e1 = expf(acc[i1] - acc[i0]);
        float w0 = 1.f / (1.f + e1);
        g_topw[2 * warp]     = w0;
        g_topw[2 * warp + 1] = e1 * w0;
        int p0 = atomicAdd(&g_cnt[i0], 1);
        g_entry[i0 * T_TOK + p0] = warp * 2;
        int p1 = atomicAdd(&g_cnt[i1], 1);
        g_entry[i1 * T_TOK + p1] = warp * 2 + 1;
    }
}

__global__ void aux_kernel(float* out, int has_aux) {
    if (!has_aux) return;
    float s = 0.f;
#pragma unroll
    for (int e = 0; e < NE; e++) { float u = g_usage[e] / (float)T_TOK; s += u * u; }
    out[(size_t)T_TOK * DIM] = (float)NE * s;
}

// ------------------------- elementwise fp32 -> bf16 hi/lo split -------------------------
// which: 0=x, 1=w1, 2=w3, 3=w2. Destination globals resolved IN DEVICE CODE
// (passing __device__ symbols as host-side kernel args was the R3/R4/R11 zero-output bug).
__global__ void conv_split_kernel(const float4* __restrict__ src, int which, int n4) {
    int i = blockIdx.x * blockDim.x + threadIdx.x;
    if (i >= n4) return;
    uint2* dh; uint2* dl;
    switch (which) {
        case 0:  dh = (uint2*)g_xh;  dl = (uint2*)g_xl;  break;
        case 1:  dh = (uint2*)g_w1h; dl = (uint2*)g_w1l; break;
        case 2:  dh = (uint2*)g_w3h; dl = (uint2*)g_w3l; break;
        default: dh = (uint2*)g_w2h; dl = (uint2*)g_w2l; break;
    }
    float4 v = src[i];
    uint32_t h01, l01, h23, l23;
    split2(v.x, v.y, h01, l01);
    split2(v.z, v.w, h23, l23);
    dh[i] = make_uint2(h01, h23);
    dl[i] = make_uint2(l01, l23);
}

// ------------------------- GEMM 1&3 fused over experts -------------------------
// grid (T_TOK/128, HID/64, NE); CTA 128x64; warp m32 x n32 (c1 AND c3).
#define NCH13 (DIM / KCH)

__global__ __launch_bounds__(256, 2)
void gemm13_mma_kernel()
{
    __shared__ uint32_t sAh[2][128][PADA], sAl[2][128][PADA];
    __shared__ uint32_t sB1h[2][16][PADB], sB1l[2][16][PADB];
    __shared__ uint32_t sB3h[2][16][PADB], sB3l[2][16][PADB];

    int e = blockIdx.z;
    int n = g_cnt[e];
    int rowBase = blockIdx.x * 128;
    if (rowBase >= n) return;
    int colBase = blockIdx.y * 64;
    int tid = threadIdx.x, wid = tid >> 5, lane = tid & 31;
    int m0 = (wid & 3) * 32, n0 = (wid >> 2) * 32;
    int grp = lane >> 2, t4 = lane & 3;

    // ---- loader coords ----
    int arow = tid >> 1, ahalf = tid & 1;                // A: 128 rows x 2 16B-chunks
    int rA = rowBase + arow;
    int slotA = (rA < n) ? g_entry[e * T_TOK + rA] : 0;
    const __nv_bfloat16* srcAh = g_xh + (size_t)(slotA >> 1) * DIM + ahalf * 8;
    const __nv_bfloat16* srcAl = g_xl + (size_t)(slotA >> 1) * DIM + ahalf * 8;

    int bidx = tid & 127, bk = bidx >> 3, bseg = bidx & 7;   // B: 16 rows x 8 chunks
    int isB3 = tid >> 7;
    const size_t ebW = (size_t)e * DIM * HID;
    const __nv_bfloat16* srcBh = (isB3 ? g_w3h : g_w1h) + ebW + (size_t)bk * HID + colBase + bseg * 8;
    const __nv_bfloat16* srcBl = (isB3 ? g_w3l : g_w1l) + ebW + (size_t)bk * HID + colBase + bseg * 8;

    uint32_t dAh[2], dAl[2], dBh[2], dBl[2];
#pragma unroll
    for (int st = 0; st < 2; st++) {
        dAh[st] = smem_to_u32(sAh[st]) + arow * (PADA * 4) + ahalf * 16;
        dAl[st] = smem_to_u32(sAl[st]) + arow * (PADA * 4) + ahalf * 16;
        dBh[st] = smem_to_u32(isB3 ? sB3h[st] : sB1h[st]) + bk * (PADB * 4) + bseg * 16;
        dBl[st] = smem_to_u32(isB3 ? sB3l[st] : sB1l[st]) + bk * (PADB * 4) + bseg * 16;
    }

    auto issue = [&](int st) {
        CP16(dAh[st], srcAh); srcAh += KCH;
        CP16(dAl[st], srcAl); srcAl += KCH;
        CP16(dBh[st], srcBh); srcBh += (size_t)KCH * HID;
        CP16(dBl[st], srcBl); srcBl += (size_t)KCH * HID;
    };

    // ---- fragment bases ----
    uint32_t loA = lane_offA(lane), loB = lane_offB(lane);
    uint32_t bAH[2], bAL[2], b1H[2], b1L[2], b3H[2], b3L[2];
#pragma unroll
    for (int st = 0; st < 2; st++) {
        bAH[st] = smem_to_u32(sAh[st]) + loA + (uint32_t)m0 * (PADA * 4);
        bAL[st] = smem_to_u32(sAl[st]) + loA + (uint32_t)m0 * (PADA * 4);
        b1H[st] = smem_to_u32(sB1h[st]) + loB + (uint32_t)n0 * 2;
        b1L[st] = smem_to_u32(sB1l[st]) + loB + (uint32_t)n0 * 2;
        b3H[st] = smem_to_u32(sB3h[st]) + loB + (uint32_t)n0 * 2;
        b3L[st] = smem_to_u32(sB3l[st]) + loB + (uint32_t)n0 * 2;
    }

    float c1[2][4][4], c3[2][4][4];
#pragma unroll
    for (int mt = 0; mt < 2; mt++)
#pragma unroll
        for (int j = 0; j < 4; j++)
#pragma unroll
            for (int q = 0; q < 4; q++) { c1[mt][j][q] = 0.f; c3[mt][j][q] = 0.f; }

    issue(0); CP_COMMIT();

    for (int c = 0; c < NCH13; c++) {
        int st = c & 1;
        CP_WAIT0();
        __syncthreads();                     // stage st ready; stage st^1 free (mma(c-1) done)
        if (c + 1 < NCH13) { issue(st ^ 1); CP_COMMIT(); }
        uint32_t ah[2][4], al[2][4];
#pragma unroll
        for (int mt = 0; mt < 2; mt++) {
            ldm_x4(ah[mt], bAH[st] + mt * 16 * (PADA * 4));
            ldm_x4(al[mt], bAL[st] + mt * 16 * (PADA * 4));
        }
#pragma unroll
        for (int nh = 0; nh < 2; nh++) {
            uint32_t f1h[4], f1l[4], f3h[4], f3l[4];
            ldm_x4_t(f1h, b1H[st] + nh * 32);
            ldm_x4_t(f1l, b1L[st] + nh * 32);
            ldm_x4_t(f3h, b3H[st] + nh * 32);
            ldm_x4_t(f3l, b3L[st] + nh * 32);
#pragma unroll
            for (int j = 0; j < 2; j++) {
                int nt = nh * 2 + j;
                uint32_t b1hF[2] = { f1h[2 * j], f1h[2 * j + 1] };
                uint32_t b1lF[2] = { f1l[2 * j], f1l[2 * j + 1] };
                uint32_t b3hF[2] = { f3h[2 * j], f3h[2 * j + 1] };
                uint32_t b3lF[2] = { f3l[2 * j], f3l[2 * j + 1] };
#pragma unroll
                for (int mt = 0; mt < 2; mt++) {
                    mma16816(c1[mt][nt], ah[mt], b1hF);
                    mma16816(c1[mt][nt], ah[mt], b1lF);
                    mma16816(c1[mt][nt], al[mt], b1hF);
                    mma16816(c3[mt][nt], ah[mt], b3hF);
                    mma16816(c3[mt][nt], ah[mt], b3lF);
                    mma16816(c3[mt][nt], al[mt], b3hF);
                }
            }
        }
    }

    // epilogue: h = silu(c1) * c3 -> bf16 hi/lo at g_Hh/g_Hl[slot]
#pragma unroll
    for (int mt = 0; mt < 2; mt++)
#pragma unroll
        for (int hf = 0; hf < 2; hf++) {
            int rr = m0 + mt * 16 + grp + hf * 8;
            int r = rowBase + rr;
            if (r < n) {
                int slot = g_entry[e * T_TOK + r];
#pragma unroll
                for (int nt = 0; nt < 4; nt++) {
                    int col = colBase + n0 + nt * 8 + t4 * 2;
                    float a0 = c1[mt][nt][hf * 2 + 0], b0 = c3[mt][nt][hf * 2 + 0];
                    float a1 = c1[mt][nt][hf * 2 + 1], b1 = c3[mt][nt][hf * 2 + 1];
                    float h0 = (a0 / (1.f + expf(-a0))) * b0;
                    float h1 = (a1 / (1.f + expf(-a1))) * b1;
                    uint32_t hh, ll;
                    split2(h0, h1, hh, ll);
                    *(uint32_t*)(g_Hh + (size_t)slot * HID + col) = hh;
                    *(uint32_t*)(g_Hl + (size_t)slot * HID + col) = ll;
                }
            }
        }
}

// ------------------------- GEMM 2 fused over experts -------------------------
// grid (T_TOK/128, DIM/64, NE); CTA 128x64; warp m32 x n32. atomicAdd into out.
#define NCH2 (HID / KCH)

__global__ __launch_bounds__(256, 2)
void gemm2_mma_kernel(float* __restrict__ out)
{
    __shared__ uint32_t sAh[2][128][PADA], sAl[2][128][PADA];
    __shared__ uint32_t sBh[2][16][PADB], sBl[2][16][PADB];
    __shared__ int sSlot[128];

    int e = blockIdx.z;
    int n = g_cnt[e];
    int rowBase = blockIdx.x * 128;
    if (rowBase >= n) return;
    int colBase = blockIdx.y * 64;
    int tid = threadIdx.x, wid = tid >> 5, lane = tid & 31;
    int m0 = (wid & 3) * 32, n0 = (wid >> 2) * 32;
    int grp = lane >> 2, t4 = lane & 3;

    if (tid < 128) {
        int r = rowBase + tid;
        sSlot[tid] = (r < n) ? g_entry[e * T_TOK + r] : 0;
    }
    __syncthreads();

    int arow = tid >> 1, ahalf = tid & 1;
    const __nv_bfloat16* srcAh = g_Hh + (size_t)sSlot[arow] * HID + ahalf * 8;
    const __nv_bfloat16* srcAl = g_Hl + (size_t)sSlot[arow] * HID + ahalf * 8;

    int bidx = tid & 127, bk = bidx >> 3, bseg = bidx & 7;
    int half2 = tid >> 7;   // threads 128-255 idle for B
    const size_t ebW = (size_t)e * HID * DIM;
    const __nv_bfloat16* srcBh = g_w2h + ebW + (size_t)bk * DIM + colBase + bseg * 8;
    const __nv_bfloat16* srcBl = g_w2l + ebW + (size_t)bk * DIM + colBase + bseg * 8;

    uint32_t dAh[2], dAl[2], dBh[2], dBl[2];
#pragma unroll
    for (int st = 0; st < 2; st++) {
        dAh[st] = smem_to_u32(sAh[st]) + arow * (PADA * 4) + ahalf * 16;
        dAl[st] = smem_to_u32(sAl[st]) + arow * (PADA * 4) + ahalf * 16;
        dBh[st] = smem_to_u32(sBh[st]) + bk * (PADB * 4) + bseg * 16;
        dBl[st] = smem_to_u32(sBl[st]) + bk * (PADB * 4) + bseg * 16;
    }

    auto issue = [&](int st) {
        CP16(dAh[st], srcAh); srcAh += KCH;
        CP16(dAl[st], srcAl); srcAl += KCH;
        if (!half2) {
            CP16(dBh[st], srcBh);
            CP16(dBl[st], srcBl);
        }
        srcBh += (size_t)KCH * DIM; srcBl += (size_t)KCH * DIM;
    };

    uint32_t loA = lane_offA(lane), loB = lane_offB(lane);
    uint32_t bAH[2], bAL[2], bBH[2], bBL[2];
#pragma unroll
    for (int st = 0; st < 2; st++) {
        bAH[st] = smem_to_u32(sAh[st]) + loA + (uint32_t)m0 * (PADA * 4);
        bAL[st] = smem_to_u32(sAl[st]) + loA + (uint32_t)m0 * (PADA * 4);
        bBH[st] = smem_to_u32(sBh[st]) + loB + (uint32_t)n0 * 2;
        bBL[st] = smem_to_u32(sBl[st]) + loB + (uint32_t)n0 * 2;
    }

    float acc[2][4][4];
#pragma unroll
    for (int mt = 0; mt < 2; mt++)
#pragma unroll
        for (int j = 0; j < 4; j++)
#pragma unroll
            for (int q = 0; q < 4; q++) acc[mt][j][q] = 0.f;

    issue(0); CP_COMMIT();

    for (int c = 0; c < NCH2; c++) {
        int st = c & 1;
        CP_WAIT0();
        __syncthreads();
        if (c + 1 < NCH2) { issue(st ^ 1); CP_COMMIT(); }
        uint32_t ah[2][4], al[2][4];
#pragma unroll
        for (int mt = 0; mt < 2; mt++) {
            ldm_x4(ah[mt], bAH[st] + mt * 16 * (PADA * 4));
            ldm_x4(al[mt], bAL[st] + mt * 16 * (PADA * 4));
        }
#pragma unroll
        for (int nh = 0; nh < 2; nh++) {
            uint32_t fh[4], fl[4];
            ldm_x4_t(fh, bBH[st] + nh * 32);
            ldm_x4_t(fl, bBL[st] + nh * 32);
#pragma unroll
            for (int j = 0; j < 2; j++) {
                int nt = nh * 2 + j;
                uint32_t bhF[2] = { fh[2 * j], fh[2 * j + 1] };
                uint32_t blF[2] = { fl[2 * j], fl[2 * j + 1] };
#pragma unroll
                for (int mt = 0; mt < 2; mt++) {
                    mma16816(acc[mt][nt], ah[mt], bhF);
                    mma16816(acc[mt][nt], ah[mt], blF);
                    mma16816(acc[mt][nt], al[mt], bhF);
                }
            }
        }
    }

    // epilogue: atomic combine into out
#pragma unroll
    for (int mt = 0; mt < 2; mt++)
#pragma unroll
        for (int hf = 0; hf < 2; hf++) {
            int rr = m0 + mt * 16 + grp + hf * 8;
            int r = rowBase + rr;
            if (r < n) {
                int slot = sSlot[rr];
                float wgt = g_topw[slot];
                float* op = out + (size_t)(slot >> 1) * DIM;
#pragma unroll
                for (int nt = 0; nt < 4; nt++) {
                    int col = colBase + n0 + nt * 8 + t4 * 2;
                    atomicAdd(op + col,     wgt * acc[mt][nt][hf * 2 + 0]);
                    atomicAdd(op + col + 1, wgt * acc[mt][nt][hf * 2 + 1]);
                }
            }
        }
}

// ------------------------- launch -------------------------
extern "C" void kernel_launch(void* const* d_in, const int* in_sizes, int n_in,
                              void* d_out, int out_size) {
    const float* x  = (const float*)d_in[0];
    const float* gw = (const float*)d_in[1];
    const float* w1 = (const float*)d_in[2];
    const float* w2 = (const float*)d_in[3];
    const float* w3 = (const float*)d_in[4];
    float* out = (float*)d_out;

    const int out_elems = T_TOK * DIM;
    const int out_elems4 = out_elems / 4;
    const int xn4 = T_TOK * DIM / 4;
    const int wn4 = NE * DIM * HID / 4;

    init_kernel<<<(out_elems4 + 255) / 256, 256>>>(out, out_elems4);
    router_kernel<<<T_TOK / 8, 256>>>(x, gw);
    aux_kernel<<<1, 1>>>(out, (out_size > out_elems) ? 1 : 0);

    conv_split_kernel<<<(xn4 + 255) / 256, 256>>>((const float4*)x, 0, xn4);
    conv_split_kernel<<<(wn4 + 255) / 256, 256>>>((const float4*)w1, 1, wn4);
    conv_split_kernel<<<(wn4 + 255) / 256, 256>>>((const float4*)w3, 2, wn4);
    conv_split_kernel<<<(wn4 + 255) / 256, 256>>>((const float4*)w2, 3, wn4);

    gemm13_mma_kernel<<<dim3(T_TOK / 128, HID / 64, NE), 256>>>();
    gemm2_mma_kernel<<<dim3(T_TOK / 128, DIM / 64, NE), 256>>>(out);
}